// round 2
// baseline (speedup 1.0000x reference)
#include <cuda_runtime.h>

#define BB 2048
#define NN 64
#define DD 512
#define HH 8
#define HDD 64
#define LL 3
#define FFD 2048
#define RR 400

// ---------------- scratch (device globals; no allocations allowed) ----------------
__device__ float g_pre[BB * NN * DD];          // e@W2 + rW1[nbr_r] + msg_b   (268 MB)
__device__ float g_rW1[RR * DD];               // emb_r @ W1
__device__ float g_Khat[LL * HH * RR * HDD];   // (emb_r @ Wk[l,h]) + bk
__device__ float g_h[BB * DD];
__device__ float g_embq[BB * DD];
__device__ float g_hW0[BB * DD];
__device__ float g_qh[BB * DD];                // [B, H*HD]
__device__ float g_ctx[BB * HH * DD];          // [B, H, D]
__device__ float g_x[BB * DD];
__device__ float g_ff[BB * FFD];

// ---------------- generic tiled fp32 GEMM ----------------
// C[m, n] (per z-slice) = act( sum_k A[row(m), z, k] * B_z[k, n] + bias_z[n] + rowadd[idx2(m), n] )
// BM=BN=64, BK=16, 256 threads, 4x4 per-thread microtile.
__global__ void __launch_bounds__(256) gemm_k(
    const float* __restrict__ A, int a_row_stride, int a_head_off,
    const int* __restrict__ a_gidx,
    const float* __restrict__ Bm, int ldb, int b_head_stride,
    const float* __restrict__ bias, int bias_head_stride,
    const float* __restrict__ rowadd, const int* __restrict__ ra_gidx,
    float* __restrict__ C, int ldc, long long c_slice_off,
    int M, int K, int act)
{
    __shared__ __align__(16) float As[16 * 68];  // [k][m], padded stride 68 (16B-aligned rows)
    __shared__ __align__(16) float Bs[16 * 64];  // [k][n]

    const int tid = threadIdx.x;
    const int tx = tid & 15, ty = tid >> 4;
    const int m0 = blockIdx.y * 64;
    const int n0 = blockIdx.x * 64;
    const int z  = blockIdx.z;

    const float* Bp = Bm + (size_t)z * b_head_stride;

    float acc[4][4];
#pragma unroll
    for (int i = 0; i < 4; i++)
#pragma unroll
        for (int j = 0; j < 4; j++) acc[i][j] = 0.f;

    // A load descriptors: element e = i*256+tid -> m = e>>4, k = e&15
    const float* ap[4];
    int am[4], ak[4];
#pragma unroll
    for (int i = 0; i < 4; i++) {
        int e = i * 256 + tid;
        am[i] = e >> 4;
        ak[i] = e & 15;
        int mrow = m0 + am[i];
        int r = (mrow < M) ? (a_gidx ? a_gidx[mrow] : mrow) : 0;
        ap[i] = A + (size_t)r * a_row_stride + (size_t)z * a_head_off + ak[i];
    }
    // B load descriptors: element e -> n = e&63, k = e>>6
    const float* bp[4];
    int bn[4], bkk[4];
#pragma unroll
    for (int i = 0; i < 4; i++) {
        int e = i * 256 + tid;
        bn[i]  = e & 63;
        bkk[i] = e >> 6;
        bp[i]  = Bp + (size_t)bkk[i] * ldb + n0 + bn[i];
    }
    const size_t bstep = (size_t)16 * ldb;

    const int ktiles = K >> 4;
    for (int t = 0; t < ktiles; t++) {
        float av[4], bv[4];
#pragma unroll
        for (int i = 0; i < 4; i++) { av[i] = ap[i][0]; ap[i] += 16; }
#pragma unroll
        for (int i = 0; i < 4; i++) { bv[i] = bp[i][0]; bp[i] += bstep; }
        __syncthreads();
#pragma unroll
        for (int i = 0; i < 4; i++) As[ak[i] * 68 + am[i]] = av[i];
#pragma unroll
        for (int i = 0; i < 4; i++) Bs[bkk[i] * 64 + bn[i]] = bv[i];
        __syncthreads();
#pragma unroll
        for (int kk = 0; kk < 16; kk++) {
            float4 a = *(const float4*)&As[kk * 68 + ty * 4];
            float4 b = *(const float4*)&Bs[kk * 64 + tx * 4];
            acc[0][0] += a.x * b.x; acc[0][1] += a.x * b.y; acc[0][2] += a.x * b.z; acc[0][3] += a.x * b.w;
            acc[1][0] += a.y * b.x; acc[1][1] += a.y * b.y; acc[1][2] += a.y * b.z; acc[1][3] += a.y * b.w;
            acc[2][0] += a.z * b.x; acc[2][1] += a.z * b.y; acc[2][2] += a.z * b.z; acc[2][3] += a.z * b.w;
            acc[3][0] += a.w * b.x; acc[3][1] += a.w * b.y; acc[3][2] += a.w * b.z; acc[3][3] += a.w * b.w;
        }
    }

    // epilogue
    const float* biasp = bias ? (bias + (size_t)z * bias_head_stride) : nullptr;
    float bcol[4];
#pragma unroll
    for (int j = 0; j < 4; j++) bcol[j] = biasp ? biasp[n0 + tx * 4 + j] : 0.f;

    float* Cp = C + (size_t)c_slice_off * z;
#pragma unroll
    for (int i = 0; i < 4; i++) {
        int m = m0 + ty * 4 + i;
        if (m < M) {
            float ra[4] = {0.f, 0.f, 0.f, 0.f};
            if (rowadd) {
                const float* rp = rowadd + (size_t)ra_gidx[m] * DD + n0 + tx * 4;
#pragma unroll
                for (int j = 0; j < 4; j++) ra[j] = rp[j];
            }
            float4 o;
            o.x = acc[i][0] + bcol[0] + ra[0];
            o.y = acc[i][1] + bcol[1] + ra[1];
            o.z = acc[i][2] + bcol[2] + ra[2];
            o.w = acc[i][3] + bcol[3] + ra[3];
            if (act == 1) {
                o.x = fmaxf(o.x, 0.f); o.y = fmaxf(o.y, 0.f);
                o.z = fmaxf(o.z, 0.f); o.w = fmaxf(o.w, 0.f);
            }
            *(float4*)&Cp[(size_t)m * ldc + n0 + tx * 4] = o;
        }
    }
}

// ---------------- fused attention (one CTA per batch row; warp == head) ----------------
__global__ void __launch_bounds__(256) attn_k(
    const float* __restrict__ qh, const float* __restrict__ Khat,  // Khat: [H, R, HD] (this layer)
    const int* __restrict__ nbr_r, const float* __restrict__ masks,
    const float* __restrict__ hW0, const float* __restrict__ pre,
    float* __restrict__ ctx)
{
    const int b = blockIdx.x;
    const int tid = threadIdx.x;
    const int lane = tid & 31, w = tid >> 5;  // warp w handles head w

    __shared__ float s_q[HH * HDD];
    __shared__ float s_attn[HH * NN];
    __shared__ int   s_nbr[NN];

    s_q[tid]       = qh[(size_t)b * DD + tid];
    s_q[tid + 256] = qh[(size_t)b * DD + tid + 256];
    if (tid < NN) s_nbr[tid] = nbr_r[b * NN + tid];
    __syncthreads();

    // scores
    {
        float q0 = s_q[w * 64 + lane], q1 = s_q[w * 64 + lane + 32];
        for (int n = 0; n < NN; n++) {
            int j = s_nbr[n];
            const float* kr = Khat + ((size_t)w * RR + j) * HDD;
            float p = q0 * kr[lane] + q1 * kr[lane + 32];
#pragma unroll
            for (int o = 16; o; o >>= 1) p += __shfl_xor_sync(0xffffffffu, p, o);
            if (lane == 0)
                s_attn[w * 64 + n] = p * 0.125f - 1e31f * (1.0f - masks[b * NN + n]);
        }
    }
    __syncwarp();
    // softmax per head
    {
        float s0 = s_attn[w * 64 + lane], s1 = s_attn[w * 64 + lane + 32];
        float m = fmaxf(s0, s1);
#pragma unroll
        for (int o = 16; o; o >>= 1) m = fmaxf(m, __shfl_xor_sync(0xffffffffu, m, o));
        float e0 = expf(s0 - m), e1 = expf(s1 - m);
        float sum = e0 + e1;
#pragma unroll
        for (int o = 16; o; o >>= 1) sum += __shfl_xor_sync(0xffffffffu, sum, o);
        float inv = 1.f / sum;
        s_attn[w * 64 + lane]      = e0 * inv;
        s_attn[w * 64 + lane + 32] = e1 * inv;
    }
    __syncthreads();

    // ctx[b,h,:] = sum_n attn[h,n] * leaky(hW0[b,:] + pre[b,n,:])
    const float hw0a = hW0[(size_t)b * DD + tid];
    const float hw0b = hW0[(size_t)b * DD + tid + 256];
    float acc[HH][2];
#pragma unroll
    for (int hh = 0; hh < HH; hh++) { acc[hh][0] = 0.f; acc[hh][1] = 0.f; }

    const float* prow = pre + (size_t)b * NN * DD;
    for (int n = 0; n < NN; n++) {
        float v0 = hw0a + prow[(size_t)n * DD + tid];
        float v1 = hw0b + prow[(size_t)n * DD + tid + 256];
        v0 = (v0 > 0.f) ? v0 : 0.01f * v0;
        v1 = (v1 > 0.f) ? v1 : 0.01f * v1;
#pragma unroll
        for (int hh = 0; hh < HH; hh++) {
            float a = s_attn[hh * 64 + n];
            acc[hh][0] += a * v0;
            acc[hh][1] += a * v1;
        }
    }
#pragma unroll
    for (int hh = 0; hh < HH; hh++) {
        ctx[((size_t)b * HH + hh) * DD + tid]       = acc[hh][0];
        ctx[((size_t)b * HH + hh) * DD + tid + 256] = acc[hh][1];
    }
}

// ---------------- layernorm: h = LN(h + x) * g + b  (biased var, eps 1e-5) ----------------
__global__ void __launch_bounds__(128) ln_k(
    float* __restrict__ h, const float* __restrict__ x,
    const float* __restrict__ gamma, const float* __restrict__ beta)
{
    const int b = blockIdx.x, tid = threadIdx.x;
    __shared__ float sred[8];
    float4 hv = ((const float4*)(h + (size_t)b * DD))[tid];
    float4 xv = ((const float4*)(x + (size_t)b * DD))[tid];
    float v0 = hv.x + xv.x, v1 = hv.y + xv.y, v2 = hv.z + xv.z, v3 = hv.w + xv.w;

    float s = v0 + v1 + v2 + v3;
#pragma unroll
    for (int o = 16; o; o >>= 1) s += __shfl_xor_sync(0xffffffffu, s, o);
    if ((tid & 31) == 0) sred[tid >> 5] = s;
    __syncthreads();
    float mean = (sred[0] + sred[1] + sred[2] + sred[3]) * (1.f / 512.f);

    v0 -= mean; v1 -= mean; v2 -= mean; v3 -= mean;
    float sq = v0 * v0 + v1 * v1 + v2 * v2 + v3 * v3;
#pragma unroll
    for (int o = 16; o; o >>= 1) sq += __shfl_xor_sync(0xffffffffu, sq, o);
    if ((tid & 31) == 0) sred[4 + (tid >> 5)] = sq;
    __syncthreads();
    float var = (sred[4] + sred[5] + sred[6] + sred[7]) * (1.f / 512.f);
    float rstd = rsqrtf(var + 1e-5f);

    float4 g = ((const float4*)gamma)[tid];
    float4 be = ((const float4*)beta)[tid];
    float4 o;
    o.x = v0 * rstd * g.x + be.x;
    o.y = v1 * rstd * g.y + be.y;
    o.z = v2 * rstd * g.z + be.z;
    o.w = v3 * rstd * g.w + be.w;
    ((float4*)(h + (size_t)b * DD))[tid] = o;
}

// ---------------- init: gather h = emb_e[e1], embq = emb_r[q]; write emb_q output half ----------------
__global__ void __launch_bounds__(128) init_k(
    const int* __restrict__ e1, const int* __restrict__ qi,
    const float* __restrict__ emb_e, const float* __restrict__ emb_r,
    float* __restrict__ h, float* __restrict__ embq,
    float* __restrict__ outq, int writeq)
{
    const int b = blockIdx.x, t = threadIdx.x;
    const float* se = emb_e + (size_t)e1[b] * DD;
    const float* sr = emb_r + (size_t)qi[b] * DD;
    for (int j = t; j < DD; j += 128) {
        h[(size_t)b * DD + j] = se[j];
        float q = sr[j];
        embq[(size_t)b * DD + j] = q;
        if (writeq) outq[(size_t)b * DD + j] = q;
    }
}

__global__ void copy_k(float* __restrict__ out, const float* __restrict__ in)
{
    int i = blockIdx.x * 256 + threadIdx.x;
    out[i] = in[i];
}

// ---------------- launch ----------------
extern "C" void kernel_launch(void* const* d_in, const int* in_sizes, int n_in,
                              void* d_out, int out_size)
{
    const int*   e1    = (const int*)d_in[0];
    const int*   qidx  = (const int*)d_in[1];
    const int*   nbr_r = (const int*)d_in[2];
    const int*   nbr_e = (const int*)d_in[3];
    const float* masks = (const float*)d_in[4];
    const float* emb_e = (const float*)d_in[5];
    const float* emb_r = (const float*)d_in[6];
    const float* msg_W = (const float*)d_in[7];
    const float* msg_b = (const float*)d_in[8];
    const float* Wq    = (const float*)d_in[9];
    const float* bq    = (const float*)d_in[10];
    const float* Wk    = (const float*)d_in[11];
    const float* bk    = (const float*)d_in[12];
    const float* Wv    = (const float*)d_in[13];
    const float* bv    = (const float*)d_in[14];
    const float* ffW1  = (const float*)d_in[15];
    const float* ffb1  = (const float*)d_in[16];
    const float* ffW2  = (const float*)d_in[17];
    const float* ffb2  = (const float*)d_in[18];
    const float* ln1g  = (const float*)d_in[19];
    const float* ln1b  = (const float*)d_in[20];
    const float* ln2g  = (const float*)d_in[21];
    const float* ln2b  = (const float*)d_in[22];
    float* out = (float*)d_out;

    float *p_pre, *p_rW1, *p_Khat, *p_h, *p_embq, *p_hW0, *p_qh, *p_ctx, *p_x, *p_ff;
    cudaGetSymbolAddress((void**)&p_pre,  g_pre);
    cudaGetSymbolAddress((void**)&p_rW1,  g_rW1);
    cudaGetSymbolAddress((void**)&p_Khat, g_Khat);
    cudaGetSymbolAddress((void**)&p_h,    g_h);
    cudaGetSymbolAddress((void**)&p_embq, g_embq);
    cudaGetSymbolAddress((void**)&p_hW0,  g_hW0);
    cudaGetSymbolAddress((void**)&p_qh,   g_qh);
    cudaGetSymbolAddress((void**)&p_ctx,  g_ctx);
    cudaGetSymbolAddress((void**)&p_x,    g_x);
    cudaGetSymbolAddress((void**)&p_ff,   g_ff);

    int writeq = (out_size >= 2 * BB * DD) ? 1 : 0;
    init_k<<<BB, 128>>>(e1, qidx, emb_e, emb_r, p_h, p_embq, out + (size_t)BB * DD, writeq);

    // rW1[j,:] = emb_r[j] @ W1   (W1 = msg_W rows 512..1023)
    gemm_k<<<dim3(8, 7, 1), 256>>>(emb_r, DD, 0, nullptr,
                                   msg_W + 512 * 512, 512, 0,
                                   nullptr, 0, nullptr, nullptr,
                                   p_rW1, 512, 0, RR, 512, 0);
    // Khat[l,h,j,:] = emb_r[j] @ Wk[l,h] + bk[l,h]   (z = l*8+h)
    gemm_k<<<dim3(1, 7, LL * HH), 256>>>(emb_r, DD, 0, nullptr,
                                         Wk, 64, DD * HDD,
                                         bk, HDD, nullptr, nullptr,
                                         p_Khat, HDD, (long long)RR * HDD, RR, 512, 0);
    // pre[b,n,:] = emb_e[nbr_e[b,n]] @ W2 + msg_b + rW1[nbr_r[b,n]]
    gemm_k<<<dim3(8, 2048, 1), 256>>>(emb_e, DD, 0, nbr_e,
                                      msg_W + 1024 * 512, 512, 0,
                                      msg_b, 0, p_rW1, nbr_r,
                                      p_pre, 512, 0, BB * NN, 512, 0);

    for (int l = 0; l < LL; l++) {
        // hW0 = h @ W0
        gemm_k<<<dim3(8, 32, 1), 256>>>(p_h, DD, 0, nullptr,
                                        msg_W, 512, 0,
                                        nullptr, 0, nullptr, nullptr,
                                        p_hW0, 512, 0, BB, 512, 0);
        // qh[b, h*64+e] = embq @ Wq[l,h] + bq[l,h]   (z = head)
        gemm_k<<<dim3(1, 32, HH), 256>>>(p_embq, DD, 0, nullptr,
                                         Wq + (size_t)l * HH * DD * HDD, HDD, DD * HDD,
                                         bq + l * HH * HDD, HDD, nullptr, nullptr,
                                         p_qh, 512, 64, BB, 512, 0);
        // fused scores + softmax + ctx accumulation
        attn_k<<<BB, 256>>>(p_qh, p_Khat + (size_t)l * HH * RR * HDD,
                            nbr_r, masks, p_hW0, p_pre, p_ctx);
        // x[b, h*64+e] = ctx[b,h] @ Wv[l,h] + bv[l,h]
        gemm_k<<<dim3(1, 32, HH), 256>>>(p_ctx, HH * DD, DD, nullptr,
                                         Wv + (size_t)l * HH * DD * HDD, HDD, DD * HDD,
                                         bv + l * HH * HDD, HDD, nullptr, nullptr,
                                         p_x, 512, 64, BB, 512, 0);
        // h = LN1(h + x)
        ln_k<<<BB, 128>>>(p_h, p_x, ln1g + l * 512, ln1b + l * 512);
        // ff = relu(h @ ffW1 + b1)
        gemm_k<<<dim3(32, 32, 1), 256>>>(p_h, DD, 0, nullptr,
                                         ffW1 + (size_t)l * DD * FFD, FFD, 0,
                                         ffb1 + l * FFD, 0, nullptr, nullptr,
                                         p_ff, FFD, 0, BB, 512, 1);
        // x = ff @ ffW2 + b2
        gemm_k<<<dim3(8, 32, 1), 256>>>(p_ff, FFD, 0, nullptr,
                                        ffW2 + (size_t)l * FFD * DD, DD, 0,
                                        ffb2 + l * DD, 0, nullptr, nullptr,
                                        p_x, DD, 0, BB, 2048, 0);
        // h = LN2(h + x)
        ln_k<<<BB, 128>>>(p_h, p_x, ln2g + l * 512, ln2b + l * 512);
    }

    copy_k<<<(BB * DD) / 256, 256>>>(out, p_h);
}

// round 4
// speedup vs baseline: 1.1474x; 1.1474x over previous
#include <cuda_runtime.h>
#include <cuda_bf16.h>
#include <cstdint>

#define BB 2048
#define NN 64
#define DD 512
#define HH 8
#define LL 3
#define FFD 2048
#define RR 400

// ---------------- device scratch ----------------
__device__ __align__(256) __nv_bfloat16 g_embe2[100000 * 1024];
__device__ __align__(256) __nv_bfloat16 g_embr2[RR * 1024];
__device__ __align__(256) __nv_bfloat16 g_embq2[BB * 1024];
__device__ __align__(256) __nv_bfloat16 g_h2[BB * 1024];
__device__ __align__(256) __nv_bfloat16 g_ctx2[BB * HH * 1024];
__device__ __align__(256) __nv_bfloat16 g_ff2[BB * 4096];
__device__ __align__(256) __nv_bfloat16 g_bW0[512 * 1024];
__device__ __align__(256) __nv_bfloat16 g_bW1[512 * 1024];
__device__ __align__(256) __nv_bfloat16 g_bW2[512 * 1024];
__device__ __align__(256) __nv_bfloat16 g_bWq[LL * 512 * 1024];
__device__ __align__(256) __nv_bfloat16 g_bWk[LL * 512 * 1024];
__device__ __align__(256) __nv_bfloat16 g_bWv[LL * 512 * 1024];
__device__ __align__(256) __nv_bfloat16 g_bF1[LL * 2048 * 1024];
__device__ __align__(256) __nv_bfloat16 g_bF2[LL * 512 * 4096];
__device__ __align__(256) float g_pre[BB * NN * 512];
__device__ __align__(256) float g_rW1[RR * 512];
__device__ __align__(256) float g_Khat[LL * RR * 512];
__device__ __align__(256) float g_h[BB * 512];
__device__ __align__(256) float g_hW0[BB * 512];
__device__ __align__(256) float g_qh[BB * 512];
__device__ __align__(256) float g_x[BB * 512];

// ---------------- helpers ----------------
__device__ __forceinline__ uint32_t s2u(const void* p) {
    uint32_t a;
    asm("{ .reg .u64 t; cvta.to.shared.u64 t, %1; cvt.u32.u64 %0, t; }" : "=r"(a) : "l"(p));
    return a;
}
__device__ __forceinline__ void cp16(uint32_t d, const void* s) {
    asm volatile("cp.async.cg.shared.global [%0], [%1], 16;" :: "r"(d), "l"(s));
}
__device__ __forceinline__ void cp_commit() { asm volatile("cp.async.commit_group;" ::: "memory"); }
template<int G> __device__ __forceinline__ void cp_wait() {
    asm volatile("cp.async.wait_group %0;" :: "n"(G) : "memory");
}
__device__ __forceinline__ void ldm4(uint32_t& r0, uint32_t& r1, uint32_t& r2, uint32_t& r3, uint32_t a) {
    asm volatile("ldmatrix.sync.aligned.m8n8.x4.shared.b16 {%0,%1,%2,%3}, [%4];"
        : "=r"(r0), "=r"(r1), "=r"(r2), "=r"(r3) : "r"(a));
}
__device__ __forceinline__ void mma16816(float* c, const uint32_t* a, const uint32_t* b) {
    asm volatile(
        "mma.sync.aligned.m16n8k16.row.col.f32.bf16.bf16.f32 "
        "{%0,%1,%2,%3}, {%4,%5,%6,%7}, {%8,%9}, {%0,%1,%2,%3};"
        : "+f"(c[0]), "+f"(c[1]), "+f"(c[2]), "+f"(c[3])
        : "r"(a[0]), "r"(a[1]), "r"(a[2]), "r"(a[3]), "r"(b[0]), "r"(b[1]));
}
__device__ __forceinline__ void bf16pair(float x, __nv_bfloat16& h, __nv_bfloat16& l) {
    h = __float2bfloat16_rn(x);
    l = __float2bfloat16_rn(x - __bfloat162float(h));
}
// 16B-chunk swizzle within a 64B row (rows repeat every 8): conflict-free ldmatrix
__device__ __forceinline__ int swz4(int row, int c) {
    int s = row & 7;
    return ((c + (s >> 2)) ^ (s & 3)) & 3;
}

// ---------------- HMMA split-bf16 GEMM ----------------
// C[m,n] = sum_k Af32[row(m),k] * Bf32[k,n] via hi/lo split (3 MMA segments).
// A: [rows][2K] bf16 (hi|lo), gathered by gidx, + z*za elem offset.
// B2: [N][2K] bf16 K-major (hi|lo), + z*zb elem offset. BM=128, BK=32.
template<int BN>
__global__ void __launch_bounds__(256) gemm_h(
    const __nv_bfloat16* __restrict__ A, int a_ld, int za,
    const int* __restrict__ gidx, int M,
    const __nv_bfloat16* __restrict__ B2, int zb, int K,
    const float* __restrict__ bias,
    const float* __restrict__ rowadd, const int* __restrict__ ridx,
    float* __restrict__ C, int ldc, int zn,
    __nv_bfloat16* __restrict__ Cbf, int cbf_ld, int cbf_half,
    int act)
{
    constexpr int WARPS_N = BN / 32;          // 4 or 2
    constexpr int WARPS_M = 8 / WARPS_N;      // 2 or 4
    constexpr int WM = 128 / WARPS_M;         // 64 or 32
    constexpr int MAT_M = WM / 16;            // 4 or 2
    constexpr int STAGE = (128 + BN) * 64;    // bytes per stage
    constexpr int UNITS = (128 + BN) * 4;     // 16B chunks per stage

    extern __shared__ __align__(1024) char smem[];
    int* s_idx = (int*)smem;
    const uint32_t sb = s2u(smem);
    const int tid = threadIdx.x, w = tid >> 5, lane = tid & 31;
    const int wm = w / WARPS_N, wn = w % WARPS_N;
    const int gm0 = blockIdx.y * 128;
    const int bn0 = blockIdx.x * BN;
    const int n0g = bn0 + (int)blockIdx.z * zn;
    const size_t zoffA = (size_t)blockIdx.z * za;
    const size_t zoffB = (size_t)blockIdx.z * zb;

    if (tid < 128) {
        int gr = gm0 + tid;
        if (gr >= M) gr = M - 1;
        s_idx[tid] = gidx ? gidx[gr] : gr;
    }
    __syncthreads();

    const int Kq = K >> 5;          // 32-wide k chunks per segment
    const int NCH = 3 * Kq;

    auto load_chunk = [&](int c) {
        int s = c & 3;
        int seg = c / Kq, kk = c - seg * Kq;
        int aoff = ((seg == 2) ? K : 0) + kk * 32;
        int boff = ((seg == 1) ? K : 0) + kk * 32;
        uint32_t st = sb + 512 + s * STAGE;
#pragma unroll
        for (int it = 0; it < UNITS / 256; it++) {
            int u = tid + it * 256;
            if (u < 512) {
                int r = u >> 2, c16 = u & 3;
                cp16(st + r * 64 + swz4(r, c16) * 16,
                     A + (size_t)s_idx[r] * a_ld + zoffA + aoff + c16 * 8);
            } else {
                int v = u - 512;
                int n = v >> 2, c16 = v & 3;
                cp16(st + 8192 + n * 64 + swz4(n, c16) * 16,
                     B2 + zoffB + (size_t)(bn0 + n) * (2 * K) + boff + c16 * 8);
            }
        }
        cp_commit();
    };

    float acc[MAT_M][4][4];
#pragma unroll
    for (int i = 0; i < MAT_M; i++)
#pragma unroll
        for (int j = 0; j < 4; j++)
#pragma unroll
            for (int q = 0; q < 4; q++) acc[i][j][q] = 0.f;

    load_chunk(0);
    load_chunk(1);
    load_chunk(2);

    const int r8 = lane & 7, sel = lane >> 3;

    for (int c = 0; c < NCH; c++) {
        cp_wait<2>();
        __syncthreads();
        uint32_t stA = sb + 512 + (c & 3) * STAGE;
        uint32_t stB = stA + 8192;
#pragma unroll
        for (int kt = 0; kt < 2; kt++) {
            uint32_t a[MAT_M][4];
#pragma unroll
            for (int i = 0; i < MAT_M; i++) {
                int ar = wm * WM + i * 16 + r8 + (sel & 1) * 8;
                int ac = kt * 2 + (sel >> 1);
                ldm4(a[i][0], a[i][1], a[i][2], a[i][3],
                     stA + ar * 64 + swz4(ar, ac) * 16);
            }
            uint32_t b[4][2];
#pragma unroll
            for (int p = 0; p < 2; p++) {
                int br = wn * 32 + p * 16 + r8 + (sel >> 1) * 8;
                int bc = kt * 2 + (sel & 1);
                uint32_t t0, t1, t2, t3;
                ldm4(t0, t1, t2, t3, stB + br * 64 + swz4(br, bc) * 16);
                b[2 * p][0] = t0; b[2 * p][1] = t1;
                b[2 * p + 1][0] = t2; b[2 * p + 1][1] = t3;
            }
#pragma unroll
            for (int i = 0; i < MAT_M; i++)
#pragma unroll
                for (int j = 0; j < 4; j++)
                    mma16816(acc[i][j], a[i], b[j]);
        }
        if (c + 3 < NCH) load_chunk(c + 3);
        else cp_commit();
    }

    // epilogue
    const int g = lane >> 2, tig = lane & 3;
#pragma unroll
    for (int i = 0; i < MAT_M; i++) {
#pragma unroll
        for (int half = 0; half < 2; half++) {
            int m = gm0 + wm * WM + i * 16 + g + half * 8;
            if (m < M) {
                const float* rp = rowadd ? (rowadd + (size_t)ridx[m] * 512) : nullptr;
#pragma unroll
                for (int j = 0; j < 4; j++) {
                    int nc = n0g + wn * 32 + j * 8 + tig * 2;
                    float v0 = acc[i][j][half * 2 + 0];
                    float v1 = acc[i][j][half * 2 + 1];
                    if (bias) { v0 += bias[nc]; v1 += bias[nc + 1]; }
                    if (rp)   { v0 += rp[nc];   v1 += rp[nc + 1]; }
                    if (act)  { v0 = fmaxf(v0, 0.f); v1 = fmaxf(v1, 0.f); }
                    if (C) {
                        float2 o; o.x = v0; o.y = v1;
                        *(float2*)&C[(size_t)m * ldc + nc] = o;
                    }
                    if (Cbf) {
                        __nv_bfloat16 h0, l0, h1, l1;
                        bf16pair(v0, h0, l0);
                        bf16pair(v1, h1, l1);
                        __nv_bfloat162 ph, pl;
                        ph.x = h0; ph.y = h1; pl.x = l0; pl.y = l1;
                        *(__nv_bfloat162*)&Cbf[(size_t)m * cbf_ld + nc] = ph;
                        *(__nv_bfloat162*)&Cbf[(size_t)m * cbf_ld + cbf_half + nc] = pl;
                    }
                }
            }
        }
    }
}

// ---------------- conversions ----------------
__global__ void __launch_bounds__(256) convW_k(
    const float* __restrict__ W, int str_k, int str_h, int K, int N,
    __nv_bfloat16* __restrict__ B2)
{
    int idx = blockIdx.x * 256 + threadIdx.x;
    if (idx >= K * N) return;
    int n = idx / K, k = idx - n * K;
    float x = W[(size_t)k * str_k + (size_t)(n >> 6) * str_h + (n & 63)];
    __nv_bfloat16 h, l; bf16pair(x, h, l);
    B2[(size_t)n * 2 * K + k] = h;
    B2[(size_t)n * 2 * K + K + k] = l;
}

__global__ void __launch_bounds__(128) convA_k(
    const float* __restrict__ src, __nv_bfloat16* __restrict__ dst)
{
    int row = blockIdx.x;
    const float* s = src + (size_t)row * 512;
    __nv_bfloat16* d = dst + (size_t)row * 1024;
    for (int k = threadIdx.x; k < 512; k += 128) {
        __nv_bfloat16 h, l; bf16pair(s[k], h, l);
        d[k] = h; d[512 + k] = l;
    }
}

// ---------------- fused attention ----------------
__global__ void __launch_bounds__(256) attn_k(
    const float* __restrict__ qh, const float* __restrict__ Khat,  // [R][512] this layer
    const int* __restrict__ nbr_r, const float* __restrict__ masks,
    const float* __restrict__ hW0, const float* __restrict__ pre,
    __nv_bfloat16* __restrict__ ctx2)
{
    const int b = blockIdx.x;
    const int tid = threadIdx.x;
    const int lane = tid & 31, w = tid >> 5;

    __shared__ float s_q[512];
    __shared__ float s_attn[HH * 64];
    __shared__ int   s_nbr[NN];

    s_q[tid]       = qh[(size_t)b * 512 + tid];
    s_q[tid + 256] = qh[(size_t)b * 512 + tid + 256];
    if (tid < NN) s_nbr[tid] = nbr_r[b * NN + tid];
    __syncthreads();

    {
        float q0 = s_q[w * 64 + lane], q1 = s_q[w * 64 + lane + 32];
        for (int n = 0; n < NN; n++) {
            int j = s_nbr[n];
            const float* kr = Khat + (size_t)j * 512 + w * 64;
            float p = q0 * kr[lane] + q1 * kr[lane + 32];
#pragma unroll
            for (int o = 16; o; o >>= 1) p += __shfl_xor_sync(0xffffffffu, p, o);
            if (lane == 0)
                s_attn[w * 64 + n] = p * 0.125f - 1e31f * (1.0f - masks[b * NN + n]);
        }
    }
    __syncwarp();
    {
        float s0 = s_attn[w * 64 + lane], s1 = s_attn[w * 64 + lane + 32];
        float m = fmaxf(s0, s1);
#pragma unroll
        for (int o = 16; o; o >>= 1) m = fmaxf(m, __shfl_xor_sync(0xffffffffu, m, o));
        float e0 = expf(s0 - m), e1 = expf(s1 - m);
        float sum = e0 + e1;
#pragma unroll
        for (int o = 16; o; o >>= 1) sum += __shfl_xor_sync(0xffffffffu, sum, o);
        float inv = 1.f / sum;
        s_attn[w * 64 + lane]      = e0 * inv;
        s_attn[w * 64 + lane + 32] = e1 * inv;
    }
    __syncthreads();

    const float hw0a = hW0[(size_t)b * 512 + tid];
    const float hw0b = hW0[(size_t)b * 512 + tid + 256];
    float acc[HH][2];
#pragma unroll
    for (int hh = 0; hh < HH; hh++) { acc[hh][0] = 0.f; acc[hh][1] = 0.f; }

    const float* prow = pre + (size_t)b * NN * 512;
    for (int n = 0; n < NN; n++) {
        float v0 = hw0a + prow[(size_t)n * 512 + tid];
        float v1 = hw0b + prow[(size_t)n * 512 + tid + 256];
        v0 = (v0 > 0.f) ? v0 : 0.01f * v0;
        v1 = (v1 > 0.f) ? v1 : 0.01f * v1;
#pragma unroll
        for (int hh = 0; hh < HH; hh++) {
            float a = s_attn[hh * 64 + n];
            acc[hh][0] += a * v0;
            acc[hh][1] += a * v1;
        }
    }
#pragma unroll
    for (int hh = 0; hh < HH; hh++) {
        __nv_bfloat16* cb = ctx2 + ((size_t)b * HH + hh) * 1024;
        __nv_bfloat16 h0, l0, h1, l1;
        bf16pair(acc[hh][0], h0, l0);
        bf16pair(acc[hh][1], h1, l1);
        cb[tid] = h0;       cb[512 + tid] = l0;
        cb[tid + 256] = h1; cb[512 + tid + 256] = l1;
    }
}

// ---------------- layernorm (+ bf16 split out) ----------------
__global__ void __launch_bounds__(128) ln_k(
    float* __restrict__ h, const float* __restrict__ x,
    const float* __restrict__ gamma, const float* __restrict__ beta,
    __nv_bfloat16* __restrict__ h2)
{
    const int b = blockIdx.x, tid = threadIdx.x;
    __shared__ float sred[8];
    float4 hv = ((const float4*)(h + (size_t)b * 512))[tid];
    float4 xv = ((const float4*)(x + (size_t)b * 512))[tid];
    float v0 = hv.x + xv.x, v1 = hv.y + xv.y, v2 = hv.z + xv.z, v3 = hv.w + xv.w;

    float s = v0 + v1 + v2 + v3;
#pragma unroll
    for (int o = 16; o; o >>= 1) s += __shfl_xor_sync(0xffffffffu, s, o);
    if ((tid & 31) == 0) sred[tid >> 5] = s;
    __syncthreads();
    float mean = (sred[0] + sred[1] + sred[2] + sred[3]) * (1.f / 512.f);

    v0 -= mean; v1 -= mean; v2 -= mean; v3 -= mean;
    float sq = v0 * v0 + v1 * v1 + v2 * v2 + v3 * v3;
#pragma unroll
    for (int o = 16; o; o >>= 1) sq += __shfl_xor_sync(0xffffffffu, sq, o);
    if ((tid & 31) == 0) sred[4 + (tid >> 5)] = sq;
    __syncthreads();
    float var = (sred[4] + sred[5] + sred[6] + sred[7]) * (1.f / 512.f);
    float rstd = rsqrtf(var + 1e-5f);

    float4 g = ((const float4*)gamma)[tid];
    float4 be = ((const float4*)beta)[tid];
    float o0 = v0 * rstd * g.x + be.x;
    float o1 = v1 * rstd * g.y + be.y;
    float o2 = v2 * rstd * g.z + be.z;
    float o3 = v3 * rstd * g.w + be.w;
    float4 o; o.x = o0; o.y = o1; o.z = o2; o.w = o3;
    ((float4*)(h + (size_t)b * 512))[tid] = o;

    __nv_bfloat16* d = h2 + (size_t)b * 1024 + tid * 4;
    __nv_bfloat16 hh, ll;
    bf16pair(o0, hh, ll); d[0] = hh; d[512] = ll;
    bf16pair(o1, hh, ll); d[1] = hh; d[513] = ll;
    bf16pair(o2, hh, ll); d[2] = hh; d[514] = ll;
    bf16pair(o3, hh, ll); d[3] = hh; d[515] = ll;
}

// ---------------- init ----------------
__global__ void __launch_bounds__(128) init_k(
    const int* __restrict__ e1, const int* __restrict__ qi,
    const float* __restrict__ emb_e, const float* __restrict__ emb_r,
    float* __restrict__ h, __nv_bfloat16* __restrict__ h2,
    __nv_bfloat16* __restrict__ embq2,
    float* __restrict__ outq, int writeq)
{
    const int b = blockIdx.x, t = threadIdx.x;
    const float* se = emb_e + (size_t)e1[b] * 512;
    const float* sr = emb_r + (size_t)qi[b] * 512;
    for (int j = t; j < 512; j += 128) {
        float hv = se[j];
        h[(size_t)b * 512 + j] = hv;
        __nv_bfloat16 hh, ll;
        bf16pair(hv, hh, ll);
        h2[(size_t)b * 1024 + j] = hh; h2[(size_t)b * 1024 + 512 + j] = ll;
        float q = sr[j];
        bf16pair(q, hh, ll);
        embq2[(size_t)b * 1024 + j] = hh; embq2[(size_t)b * 1024 + 512 + j] = ll;
        if (writeq) outq[(size_t)b * 512 + j] = q;
    }
}

__global__ void copy_k(float* __restrict__ out, const float* __restrict__ in)
{
    int i = blockIdx.x * 256 + threadIdx.x;
    out[i] = in[i];
}

// ---------------- launch ----------------
extern "C" void kernel_launch(void* const* d_in, const int* in_sizes, int n_in,
                              void* d_out, int out_size)
{
    const int*   e1    = (const int*)d_in[0];
    const int*   qidx  = (const int*)d_in[1];
    const int*   nbr_r = (const int*)d_in[2];
    const int*   nbr_e = (const int*)d_in[3];
    const float* masks = (const float*)d_in[4];
    const float* emb_e = (const float*)d_in[5];
    const float* emb_r = (const float*)d_in[6];
    const float* msg_W = (const float*)d_in[7];
    const float* msg_b = (const float*)d_in[8];
    const float* Wq    = (const float*)d_in[9];
    const float* bq    = (const float*)d_in[10];
    const float* Wk    = (const float*)d_in[11];
    const float* bk    = (const float*)d_in[12];
    const float* Wv    = (const float*)d_in[13];
    const float* bv    = (const float*)d_in[14];
    const float* ffW1  = (const float*)d_in[15];
    const float* ffb1  = (const float*)d_in[16];
    const float* ffW2  = (const float*)d_in[17];
    const float* ffb2  = (const float*)d_in[18];
    const float* ln1g  = (const float*)d_in[19];
    const float* ln1b  = (const float*)d_in[20];
    const float* ln2g  = (const float*)d_in[21];
    const float* ln2b  = (const float*)d_in[22];
    float* out = (float*)d_out;

    __nv_bfloat16 *p_embe2, *p_embr2, *p_embq2, *p_h2, *p_ctx2, *p_ff2;
    __nv_bfloat16 *p_bW0, *p_bW1, *p_bW2, *p_bWq, *p_bWk, *p_bWv, *p_bF1, *p_bF2;
    float *p_pre, *p_rW1, *p_Khat, *p_h, *p_hW0, *p_qh, *p_x;
    cudaGetSymbolAddress((void**)&p_embe2, g_embe2);
    cudaGetSymbolAddress((void**)&p_embr2, g_embr2);
    cudaGetSymbolAddress((void**)&p_embq2, g_embq2);
    cudaGetSymbolAddress((void**)&p_h2,    g_h2);
    cudaGetSymbolAddress((void**)&p_ctx2,  g_ctx2);
    cudaGetSymbolAddress((void**)&p_ff2,   g_ff2);
    cudaGetSymbolAddress((void**)&p_bW0,   g_bW0);
    cudaGetSymbolAddress((void**)&p_bW1,   g_bW1);
    cudaGetSymbolAddress((void**)&p_bW2,   g_bW2);
    cudaGetSymbolAddress((void**)&p_bWq,   g_bWq);
    cudaGetSymbolAddress((void**)&p_bWk,   g_bWk);
    cudaGetSymbolAddress((void**)&p_bWv,   g_bWv);
    cudaGetSymbolAddress((void**)&p_bF1,   g_bF1);
    cudaGetSymbolAddress((void**)&p_bF2,   g_bF2);
    cudaGetSymbolAddress((void**)&p_pre,   g_pre);
    cudaGetSymbolAddress((void**)&p_rW1,   g_rW1);
    cudaGetSymbolAddress((void**)&p_Khat,  g_Khat);
    cudaGetSymbolAddress((void**)&p_h,     g_h);
    cudaGetSymbolAddress((void**)&p_hW0,   g_hW0);
    cudaGetSymbolAddress((void**)&p_qh,    g_qh);
    cudaGetSymbolAddress((void**)&p_x,     g_x);

    const int SM128 = 512 + 4 * (256 * 64);  // 66048
    const int SM64  = 512 + 4 * (192 * 64);  // 49664
    cudaFuncSetAttribute(gemm_h<128>, cudaFuncAttributeMaxDynamicSharedMemorySize, SM128);
    cudaFuncSetAttribute(gemm_h<64>,  cudaFuncAttributeMaxDynamicSharedMemorySize, SM64);

    int writeq = (out_size >= 2 * BB * DD) ? 1 : 0;
    init_k<<<BB, 128>>>(e1, qidx, emb_e, emb_r, p_h, p_h2, p_embq2, out + (size_t)BB * DD, writeq);

    convA_k<<<100000, 128>>>(emb_e, p_embe2);
    convA_k<<<RR, 128>>>(emb_r, p_embr2);

    convW_k<<<(512 * 512 + 255) / 256, 256>>>(msg_W, 512, 64, 512, 512, p_bW0);
    convW_k<<<(512 * 512 + 255) / 256, 256>>>(msg_W + 512 * 512, 512, 64, 512, 512, p_bW1);
    convW_k<<<(512 * 512 + 255) / 256, 256>>>(msg_W + 1024 * 512, 512, 64, 512, 512, p_bW2);
    for (int l = 0; l < LL; l++) {
        convW_k<<<(512 * 512 + 255) / 256, 256>>>(Wq + (size_t)l * 512 * 512, 64, 32768, 512, 512, p_bWq + (size_t)l * 512 * 1024);
        convW_k<<<(512 * 512 + 255) / 256, 256>>>(Wk + (size_t)l * 512 * 512, 64, 32768, 512, 512, p_bWk + (size_t)l * 512 * 1024);
        convW_k<<<(512 * 512 + 255) / 256, 256>>>(Wv + (size_t)l * 512 * 512, 64, 32768, 512, 512, p_bWv + (size_t)l * 512 * 1024);
        convW_k<<<(512 * 2048 + 255) / 256, 256>>>(ffW1 + (size_t)l * 512 * 2048, 2048, 64, 512, 2048, p_bF1 + (size_t)l * 2048 * 1024);
        convW_k<<<(2048 * 512 + 255) / 256, 256>>>(ffW2 + (size_t)l * 2048 * 512, 512, 64, 2048, 512, p_bF2 + (size_t)l * 512 * 4096);
    }

    // rW1 = emb_r @ W1
    gemm_h<128><<<dim3(4, 4), 256, SM128>>>(p_embr2, 1024, 0, nullptr, RR, p_bW1, 0, 512,
                                            nullptr, nullptr, nullptr, p_rW1, 512, 0,
                                            nullptr, 0, 0, 0);
    // Khat[l] = emb_r @ Wk[l](stacked) + bk[l]
    for (int l = 0; l < LL; l++)
        gemm_h<128><<<dim3(4, 4), 256, SM128>>>(p_embr2, 1024, 0, nullptr, RR,
                                                p_bWk + (size_t)l * 512 * 1024, 0, 512,
                                                bk + l * 512, nullptr, nullptr,
                                                p_Khat + (size_t)l * RR * 512, 512, 0,
                                                nullptr, 0, 0, 0);
    // pre = gather(emb_e)[nbr_e] @ W2 + msg_b + rW1[nbr_r]
    gemm_h<128><<<dim3(4, 1024), 256, SM128>>>(p_embe2, 1024, 0, nbr_e, BB * NN, p_bW2, 0, 512,
                                               msg_b, p_rW1, nbr_r, p_pre, 512, 0,
                                               nullptr, 0, 0, 0);

    for (int l = 0; l < LL; l++) {
        // hW0 = h @ W0
        gemm_h<128><<<dim3(4, 16), 256, SM128>>>(p_h2, 1024, 0, nullptr, BB, p_bW0, 0, 512,
                                                 nullptr, nullptr, nullptr, p_hW0, 512, 0,
                                                 nullptr, 0, 0, 0);
        // qh = embq @ Wq[l](stacked) + bq[l]
        gemm_h<128><<<dim3(4, 16), 256, SM128>>>(p_embq2, 1024, 0, nullptr, BB,
                                                 p_bWq + (size_t)l * 512 * 1024, 0, 512,
                                                 bq + l * 512, nullptr, nullptr, p_qh, 512, 0,
                                                 nullptr, 0, 0, 0);
        attn_k<<<BB, 256>>>(p_qh, p_Khat + (size_t)l * RR * 512, nbr_r, masks, p_hW0, p_pre, p_ctx2);
        // x = ctx @ Wv[l] + bv[l]  (z = head)
        gemm_h<64><<<dim3(1, 16, 8), 256, SM64>>>(p_ctx2, 8192, 1024, nullptr, BB,
                                                  p_bWv + (size_t)l * 512 * 1024, 65536, 512,
                                                  bv + l * 512, nullptr, nullptr, p_x, 512, 64,
                                                  nullptr, 0, 0, 0);
        ln_k<<<BB, 128>>>(p_h, p_x, ln1g + l * 512, ln1b + l * 512, p_h2);
        // ff2 = split(relu(h @ F1 + b1))
        gemm_h<128><<<dim3(16, 16), 256, SM128>>>(p_h2, 1024, 0, nullptr, BB,
                                                  p_bF1 + (size_t)l * 2048 * 1024, 0, 512,
                                                  ffb1 + l * 2048, nullptr, nullptr,
                                                  nullptr, 0, 0, p_ff2, 4096, 2048, 1);
        // x = ff @ F2 + b2
        gemm_h<128><<<dim3(4, 16), 256, SM128>>>(p_ff2, 4096, 0, nullptr, BB,
                                                 p_bF2 + (size_t)l * 512 * 4096, 0, 2048,
                                                 ffb2 + l * 512, nullptr, nullptr, p_x, 512, 0,
                                                 nullptr, 0, 0, 0);
        ln_k<<<BB, 128>>>(p_h, p_x, ln2g + l * 512, ln2b + l * 512, p_h2);
    }

    copy_k<<<(BB * DD) / 256, 256>>>(out, p_h);
}

// round 5
// speedup vs baseline: 2.4846x; 2.1655x over previous
#include <cuda_runtime.h>
#include <cuda_bf16.h>
#include <cuda_fp16.h>
#include <cstdint>

#define BB 2048
#define NN 64
#define DD 512
#define HH 8
#define LL 3
#define FFD 2048
#define RR 400
#define EE 100000

// ---------------- device scratch ----------------
__device__ __align__(256) __half        g_embeH[EE * 512];        // emb_e fp16 single
__device__ __align__(256) __half        g_bW2h[512 * 512];        // W2 fp16 [n][k]
__device__ __align__(256) float         g_eW2[EE * 512];          // emb_e @ W2 + msg_b
__device__ __align__(256) __nv_bfloat16 g_embr2[RR * 1024];
__device__ __align__(256) __nv_bfloat16 g_embq2[BB * 1024];
__device__ __align__(256) __nv_bfloat16 g_h2[BB * 1024];
__device__ __align__(256) __nv_bfloat16 g_ctx2[BB * HH * 1024];
__device__ __align__(256) __nv_bfloat16 g_ff2[BB * 4096];
__device__ __align__(256) __nv_bfloat16 g_bW0[512 * 1024];
__device__ __align__(256) __nv_bfloat16 g_bW1[512 * 1024];
__device__ __align__(256) __nv_bfloat16 g_bWq[LL * 512 * 1024];
__device__ __align__(256) __nv_bfloat16 g_bWk[LL * 512 * 1024];
__device__ __align__(256) __nv_bfloat16 g_bWv[LL * 512 * 1024];
__device__ __align__(256) __nv_bfloat16 g_bF1[LL * 2048 * 1024];
__device__ __align__(256) __nv_bfloat16 g_bF2[LL * 512 * 4096];
__device__ __align__(256) float g_rW1[RR * 512];
__device__ __align__(256) float g_Khat[LL * RR * 512];
__device__ __align__(256) float g_h[BB * 512];
__device__ __align__(256) float g_hW0[BB * 512];
__device__ __align__(256) float g_qh[BB * 512];
__device__ __align__(256) float g_x[2 * BB * 512];

// ---------------- helpers ----------------
__device__ __forceinline__ uint32_t s2u(const void* p) {
    uint32_t a;
    asm("{ .reg .u64 t; cvta.to.shared.u64 t, %1; cvt.u32.u64 %0, t; }" : "=r"(a) : "l"(p));
    return a;
}
__device__ __forceinline__ void cp16(uint32_t d, const void* s) {
    asm volatile("cp.async.cg.shared.global [%0], [%1], 16;" :: "r"(d), "l"(s));
}
__device__ __forceinline__ void cp_commit() { asm volatile("cp.async.commit_group;" ::: "memory"); }
template<int G> __device__ __forceinline__ void cp_wait() {
    asm volatile("cp.async.wait_group %0;" :: "n"(G) : "memory");
}
__device__ __forceinline__ void ldm4(uint32_t& r0, uint32_t& r1, uint32_t& r2, uint32_t& r3, uint32_t a) {
    asm volatile("ldmatrix.sync.aligned.m8n8.x4.shared.b16 {%0,%1,%2,%3}, [%4];"
        : "=r"(r0), "=r"(r1), "=r"(r2), "=r"(r3) : "r"(a));
}
__device__ __forceinline__ void mma_bf16(float* c, const uint32_t* a, const uint32_t* b) {
    asm volatile(
        "mma.sync.aligned.m16n8k16.row.col.f32.bf16.bf16.f32 "
        "{%0,%1,%2,%3}, {%4,%5,%6,%7}, {%8,%9}, {%0,%1,%2,%3};"
        : "+f"(c[0]), "+f"(c[1]), "+f"(c[2]), "+f"(c[3])
        : "r"(a[0]), "r"(a[1]), "r"(a[2]), "r"(a[3]), "r"(b[0]), "r"(b[1]));
}
__device__ __forceinline__ void mma_f16(float* c, const uint32_t* a, const uint32_t* b) {
    asm volatile(
        "mma.sync.aligned.m16n8k16.row.col.f32.f16.f16.f32 "
        "{%0,%1,%2,%3}, {%4,%5,%6,%7}, {%8,%9}, {%0,%1,%2,%3};"
        : "+f"(c[0]), "+f"(c[1]), "+f"(c[2]), "+f"(c[3])
        : "r"(a[0]), "r"(a[1]), "r"(a[2]), "r"(a[3]), "r"(b[0]), "r"(b[1]));
}
__device__ __forceinline__ void bf16pair(float x, __nv_bfloat16& h, __nv_bfloat16& l) {
    h = __float2bfloat16_rn(x);
    l = __float2bfloat16_rn(x - __bfloat162float(h));
}
// 16B-chunk swizzle within 64B rows: conflict-free ldmatrix
__device__ __forceinline__ int swz4(int row, int c) {
    int s = row & 7;
    return ((c + (s >> 2)) ^ (s & 3)) & 3;
}

// ---------------- HMMA GEMM (split bf16 NSEG=3, or single fp16 NSEG=1) ----------------
// A: [rows][NSEG==3 ? 2K : K] 16-bit, gathered by gidx, + z*za elems.
// B2: [N][same] K-major, + z*zb elems. BM=128, BK=32 per chunk.
// kz: split-K over z (chunks [z*kspan, z*kspan+kspan)), C += z*czoff, bias only z==0.
template<int BN, int NSEG, int DT>
__global__ void __launch_bounds__(256) gemm_h(
    const __nv_bfloat16* __restrict__ A, int a_ld, int za,
    const int* __restrict__ gidx, int M,
    const __nv_bfloat16* __restrict__ B2, int zb, int K,
    const float* __restrict__ bias,
    float* __restrict__ C, int ldc, int zn, long long czoff, int kz, int kspan,
    __nv_bfloat16* __restrict__ Cbf, int cbf_ld, int cbf_half,
    int act)
{
    constexpr int WARPS_N = BN / 32;
    constexpr int WARPS_M = 8 / WARPS_N;
    constexpr int WM = 128 / WARPS_M;
    constexpr int MAT_M = WM / 16;
    constexpr int STAGE = (128 + BN) * 64;
    constexpr int UNITS = (128 + BN) * 4;

    extern __shared__ __align__(1024) char smem[];
    int* s_idx = (int*)smem;
    const uint32_t sb = s2u(smem);
    const int tid = threadIdx.x, w = tid >> 5, lane = tid & 31;
    const int wm = w / WARPS_N, wn = w % WARPS_N;
    const int gm0 = blockIdx.y * 128;
    const int bn0 = blockIdx.x * BN;
    const int n0g = bn0 + (int)blockIdx.z * zn;
    const size_t zoffA = (size_t)blockIdx.z * za;
    const size_t zoffB = (size_t)blockIdx.z * zb;
    const int brs = (NSEG == 3) ? 2 * K : K;

    if (kz && blockIdx.z > 0) bias = nullptr;
    if (kz) C += (size_t)blockIdx.z * czoff;

    if (tid < 128) {
        int gr = gm0 + tid;
        if (gr >= M) gr = M - 1;
        s_idx[tid] = gidx ? gidx[gr] : gr;
    }
    __syncthreads();

    const int Kq = K >> 5;
    const int NCH = NSEG * Kq;
    const int kbeg = kz ? (int)blockIdx.z * kspan : 0;
    const int kcnt = kz ? kspan : NCH;

    auto load_chunk = [&](int c) {
        int s = c & 3;
        int seg = (NSEG == 3) ? c / Kq : 0;
        int kk = c - seg * Kq;
        int aoff = ((seg == 2) ? K : 0) + kk * 32;
        int boff = ((seg == 1) ? K : 0) + kk * 32;
        uint32_t st = sb + 512 + s * STAGE;
#pragma unroll
        for (int it = 0; it < UNITS / 256; it++) {
            int u = tid + it * 256;
            if (u < 512) {
                int r = u >> 2, c16 = u & 3;
                cp16(st + r * 64 + swz4(r, c16) * 16,
                     A + (size_t)s_idx[r] * a_ld + zoffA + aoff + c16 * 8);
            } else {
                int v = u - 512;
                int n = v >> 2, c16 = v & 3;
                cp16(st + 8192 + n * 64 + swz4(n, c16) * 16,
                     B2 + zoffB + (size_t)(bn0 + n) * brs + boff + c16 * 8);
            }
        }
        cp_commit();
    };

    float acc[MAT_M][4][4];
#pragma unroll
    for (int i = 0; i < MAT_M; i++)
#pragma unroll
        for (int j = 0; j < 4; j++)
#pragma unroll
            for (int q = 0; q < 4; q++) acc[i][j][q] = 0.f;

    load_chunk(kbeg);
    load_chunk(kbeg + 1);
    load_chunk(kbeg + 2);

    const int r8 = lane & 7, sel = lane >> 3;

    for (int cc = 0; cc < kcnt; cc++) {
        int c = kbeg + cc;
        cp_wait<2>();
        __syncthreads();
        uint32_t stA = sb + 512 + (c & 3) * STAGE;
        uint32_t stB = stA + 8192;
#pragma unroll
        for (int kt = 0; kt < 2; kt++) {
            uint32_t a[MAT_M][4];
#pragma unroll
            for (int i = 0; i < MAT_M; i++) {
                int ar = wm * WM + i * 16 + r8 + (sel & 1) * 8;
                int ac = kt * 2 + (sel >> 1);
                ldm4(a[i][0], a[i][1], a[i][2], a[i][3],
                     stA + ar * 64 + swz4(ar, ac) * 16);
            }
            uint32_t b[4][2];
#pragma unroll
            for (int p = 0; p < 2; p++) {
                int br = wn * 32 + p * 16 + r8 + (sel >> 1) * 8;
                int bc = kt * 2 + (sel & 1);
                uint32_t t0, t1, t2, t3;
                ldm4(t0, t1, t2, t3, stB + br * 64 + swz4(br, bc) * 16);
                b[2 * p][0] = t0; b[2 * p][1] = t1;
                b[2 * p + 1][0] = t2; b[2 * p + 1][1] = t3;
            }
#pragma unroll
            for (int i = 0; i < MAT_M; i++)
#pragma unroll
                for (int j = 0; j < 4; j++) {
                    if (DT == 0) mma_bf16(acc[i][j], a[i], b[j]);
                    else         mma_f16(acc[i][j], a[i], b[j]);
                }
        }
        if (cc + 3 < kcnt) load_chunk(c + 3);
        else cp_commit();
    }

    // epilogue
    const int g = lane >> 2, tig = lane & 3;
#pragma unroll
    for (int i = 0; i < MAT_M; i++) {
#pragma unroll
        for (int half = 0; half < 2; half++) {
            int m = gm0 + wm * WM + i * 16 + g + half * 8;
            if (m < M) {
#pragma unroll
                for (int j = 0; j < 4; j++) {
                    int nc = n0g + wn * 32 + j * 8 + tig * 2;
                    float v0 = acc[i][j][half * 2 + 0];
                    float v1 = acc[i][j][half * 2 + 1];
                    if (bias) { v0 += bias[nc]; v1 += bias[nc + 1]; }
                    if (act)  { v0 = fmaxf(v0, 0.f); v1 = fmaxf(v1, 0.f); }
                    if (C) {
                        float2 o; o.x = v0; o.y = v1;
                        *(float2*)&C[(size_t)m * ldc + nc] = o;
                    }
                    if (Cbf) {
                        __nv_bfloat16 h0, l0, h1, l1;
                        bf16pair(v0, h0, l0);
                        bf16pair(v1, h1, l1);
                        __nv_bfloat162 ph, pl;
                        ph.x = h0; ph.y = h1; pl.x = l0; pl.y = l1;
                        *(__nv_bfloat162*)&Cbf[(size_t)m * cbf_ld + nc] = ph;
                        *(__nv_bfloat162*)&Cbf[(size_t)m * cbf_ld + cbf_half + nc] = pl;
                    }
                }
            }
        }
    }
}

// ---------------- conversions ----------------
__global__ void __launch_bounds__(256) convW_k(
    const float* __restrict__ W, int str_k, int str_h, int K, int N,
    __nv_bfloat16* __restrict__ B2)
{
    int idx = blockIdx.x * 256 + threadIdx.x;
    if (idx >= K * N) return;
    int n = idx / K, k = idx - n * K;
    float x = W[(size_t)k * str_k + (size_t)(n >> 6) * str_h + (n & 63)];
    __nv_bfloat16 h, l; bf16pair(x, h, l);
    B2[(size_t)n * 2 * K + k] = h;
    B2[(size_t)n * 2 * K + K + k] = l;
}

__global__ void __launch_bounds__(256) convW_h(
    const float* __restrict__ W, int K, int N, __half* __restrict__ B2)
{
    int idx = blockIdx.x * 256 + threadIdx.x;
    if (idx >= K * N) return;
    int n = idx / K, k = idx - n * K;
    B2[(size_t)n * K + k] = __float2half_rn(W[(size_t)k * N + n]);
}

__global__ void __launch_bounds__(128) convA_k(
    const float* __restrict__ src, __nv_bfloat16* __restrict__ dst)
{
    int row = blockIdx.x;
    const float* s = src + (size_t)row * 512;
    __nv_bfloat16* d = dst + (size_t)row * 1024;
    for (int k = threadIdx.x; k < 512; k += 128) {
        __nv_bfloat16 h, l; bf16pair(s[k], h, l);
        d[k] = h; d[512 + k] = l;
    }
}

__global__ void __launch_bounds__(128) convA_h(
    const float* __restrict__ src, __half* __restrict__ dst)
{
    size_t i = (size_t)blockIdx.x * 512 + threadIdx.x;
#pragma unroll
    for (int t = 0; t < 4; t++)
        dst[i + t * 128] = __float2half_rn(src[i + t * 128]);
}

// ---------------- fused attention ----------------
__global__ void __launch_bounds__(256) attn_k(
    const float* __restrict__ qh, const float* __restrict__ Khat,  // [R][512] this layer
    const int* __restrict__ nbr_r, const int* __restrict__ nbr_e,
    const float* __restrict__ masks,
    const float* __restrict__ hW0, const float* __restrict__ eW2,
    const float* __restrict__ rW1,
    __nv_bfloat16* __restrict__ ctx2)
{
    const int b = blockIdx.x;
    const int tid = threadIdx.x;
    const int lane = tid & 31, w = tid >> 5;

    __shared__ float s_q[512];
    __shared__ float s_attn[HH * 64];
    __shared__ int   s_nbr[NN], s_nbe[NN];

    s_q[tid]       = qh[(size_t)b * 512 + tid];
    s_q[tid + 256] = qh[(size_t)b * 512 + tid + 256];
    if (tid < NN) { s_nbr[tid] = nbr_r[b * NN + tid]; s_nbe[tid] = nbr_e[b * NN + tid]; }
    __syncthreads();

    {
        float q0 = s_q[w * 64 + lane], q1 = s_q[w * 64 + lane + 32];
        for (int n = 0; n < NN; n++) {
            int j = s_nbr[n];
            const float* kr = Khat + (size_t)j * 512 + w * 64;
            float p = q0 * kr[lane] + q1 * kr[lane + 32];
#pragma unroll
            for (int o = 16; o; o >>= 1) p += __shfl_xor_sync(0xffffffffu, p, o);
            if (lane == 0)
                s_attn[w * 64 + n] = p * 0.125f - 1e31f * (1.0f - masks[b * NN + n]);
        }
    }
    __syncwarp();
    {
        float s0 = s_attn[w * 64 + lane], s1 = s_attn[w * 64 + lane + 32];
        float m = fmaxf(s0, s1);
#pragma unroll
        for (int o = 16; o; o >>= 1) m = fmaxf(m, __shfl_xor_sync(0xffffffffu, m, o));
        float e0 = expf(s0 - m), e1 = expf(s1 - m);
        float sum = e0 + e1;
#pragma unroll
        for (int o = 16; o; o >>= 1) sum += __shfl_xor_sync(0xffffffffu, sum, o);
        float inv = 1.f / sum;
        s_attn[w * 64 + lane]      = e0 * inv;
        s_attn[w * 64 + lane + 32] = e1 * inv;
    }
    __syncthreads();

    const float hw0a = hW0[(size_t)b * 512 + tid];
    const float hw0b = hW0[(size_t)b * 512 + tid + 256];
    float acc[HH][2];
#pragma unroll
    for (int hh = 0; hh < HH; hh++) { acc[hh][0] = 0.f; acc[hh][1] = 0.f; }

#pragma unroll 2
    for (int n = 0; n < NN; n++) {
        const float* ep = eW2 + (size_t)s_nbe[n] * 512;
        const float* rp = rW1 + (size_t)s_nbr[n] * 512;
        float v0 = hw0a + ep[tid] + rp[tid];
        float v1 = hw0b + ep[tid + 256] + rp[tid + 256];
        v0 = (v0 > 0.f) ? v0 : 0.01f * v0;
        v1 = (v1 > 0.f) ? v1 : 0.01f * v1;
#pragma unroll
        for (int hh = 0; hh < HH; hh++) {
            float a = s_attn[hh * 64 + n];
            acc[hh][0] += a * v0;
            acc[hh][1] += a * v1;
        }
    }
#pragma unroll
    for (int hh = 0; hh < HH; hh++) {
        __nv_bfloat16* cb = ctx2 + ((size_t)b * HH + hh) * 1024;
        __nv_bfloat16 h0, l0, h1, l1;
        bf16pair(acc[hh][0], h0, l0);
        bf16pair(acc[hh][1], h1, l1);
        cb[tid] = h0;       cb[512 + tid] = l0;
        cb[tid + 256] = h1; cb[512 + tid + 256] = l1;
    }
}

// ---------------- layernorm (+ optional second x, + bf16 split out) ----------------
__global__ void __launch_bounds__(128) ln_k(
    float* __restrict__ h, const float* __restrict__ x, const float* __restrict__ x2,
    const float* __restrict__ gamma, const float* __restrict__ beta,
    __nv_bfloat16* __restrict__ h2)
{
    const int b = blockIdx.x, tid = threadIdx.x;
    __shared__ float sred[8];
    float4 hv = ((const float4*)(h + (size_t)b * 512))[tid];
    float4 xv = ((const float4*)(x + (size_t)b * 512))[tid];
    float v0 = hv.x + xv.x, v1 = hv.y + xv.y, v2 = hv.z + xv.z, v3 = hv.w + xv.w;
    if (x2) {
        float4 x2v = ((const float4*)(x2 + (size_t)b * 512))[tid];
        v0 += x2v.x; v1 += x2v.y; v2 += x2v.z; v3 += x2v.w;
    }

    float s = v0 + v1 + v2 + v3;
#pragma unroll
    for (int o = 16; o; o >>= 1) s += __shfl_xor_sync(0xffffffffu, s, o);
    if ((tid & 31) == 0) sred[tid >> 5] = s;
    __syncthreads();
    float mean = (sred[0] + sred[1] + sred[2] + sred[3]) * (1.f / 512.f);

    v0 -= mean; v1 -= mean; v2 -= mean; v3 -= mean;
    float sq = v0 * v0 + v1 * v1 + v2 * v2 + v3 * v3;
#pragma unroll
    for (int o = 16; o; o >>= 1) sq += __shfl_xor_sync(0xffffffffu, sq, o);
    if ((tid & 31) == 0) sred[4 + (tid >> 5)] = sq;
    __syncthreads();
    float var = (sred[4] + sred[5] + sred[6] + sred[7]) * (1.f / 512.f);
    float rstd = rsqrtf(var + 1e-5f);

    float4 g = ((const float4*)gamma)[tid];
    float4 be = ((const float4*)beta)[tid];
    float o0 = v0 * rstd * g.x + be.x;
    float o1 = v1 * rstd * g.y + be.y;
    float o2 = v2 * rstd * g.z + be.z;
    float o3 = v3 * rstd * g.w + be.w;
    float4 o; o.x = o0; o.y = o1; o.z = o2; o.w = o3;
    ((float4*)(h + (size_t)b * 512))[tid] = o;

    __nv_bfloat16* d = h2 + (size_t)b * 1024 + tid * 4;
    __nv_bfloat16 hh, ll;
    bf16pair(o0, hh, ll); d[0] = hh; d[512] = ll;
    bf16pair(o1, hh, ll); d[1] = hh; d[513] = ll;
    bf16pair(o2, hh, ll); d[2] = hh; d[514] = ll;
    bf16pair(o3, hh, ll); d[3] = hh; d[515] = ll;
}

// ---------------- init ----------------
__global__ void __launch_bounds__(128) init_k(
    const int* __restrict__ e1, const int* __restrict__ qi,
    const float* __restrict__ emb_e, const float* __restrict__ emb_r,
    float* __restrict__ h, __nv_bfloat16* __restrict__ h2,
    __nv_bfloat16* __restrict__ embq2,
    float* __restrict__ outq, int writeq)
{
    const int b = blockIdx.x, t = threadIdx.x;
    const float* se = emb_e + (size_t)e1[b] * 512;
    const float* sr = emb_r + (size_t)qi[b] * 512;
    for (int j = t; j < 512; j += 128) {
        float hv = se[j];
        h[(size_t)b * 512 + j] = hv;
        __nv_bfloat16 hh, ll;
        bf16pair(hv, hh, ll);
        h2[(size_t)b * 1024 + j] = hh; h2[(size_t)b * 1024 + 512 + j] = ll;
        float q = sr[j];
        bf16pair(q, hh, ll);
        embq2[(size_t)b * 1024 + j] = hh; embq2[(size_t)b * 1024 + 512 + j] = ll;
        if (writeq) outq[(size_t)b * 512 + j] = q;
    }
}

__global__ void copy_k(float* __restrict__ out, const float* __restrict__ in)
{
    int i = blockIdx.x * 256 + threadIdx.x;
    out[i] = in[i];
}

// ---------------- launch ----------------
extern "C" void kernel_launch(void* const* d_in, const int* in_sizes, int n_in,
                              void* d_out, int out_size)
{
    const int*   e1    = (const int*)d_in[0];
    const int*   qidx  = (const int*)d_in[1];
    const int*   nbr_r = (const int*)d_in[2];
    const int*   nbr_e = (const int*)d_in[3];
    const float* masks = (const float*)d_in[4];
    const float* emb_e = (const float*)d_in[5];
    const float* emb_r = (const float*)d_in[6];
    const float* msg_W = (const float*)d_in[7];
    const float* msg_b = (const float*)d_in[8];
    const float* Wq    = (const float*)d_in[9];
    const float* bq    = (const float*)d_in[10];
    const float* Wk    = (const float*)d_in[11];
    const float* bk    = (const float*)d_in[12];
    const float* Wv    = (const float*)d_in[13];
    const float* bv    = (const float*)d_in[14];
    const float* ffW1  = (const float*)d_in[15];
    const float* ffb1  = (const float*)d_in[16];
    const float* ffW2  = (const float*)d_in[17];
    const float* ffb2  = (const float*)d_in[18];
    const float* ln1g  = (const float*)d_in[19];
    const float* ln1b  = (const float*)d_in[20];
    const float* ln2g  = (const float*)d_in[21];
    const float* ln2b  = (const float*)d_in[22];
    float* out = (float*)d_out;

    __half *p_embeH, *p_bW2h;
    __nv_bfloat16 *p_embr2, *p_embq2, *p_h2, *p_ctx2, *p_ff2;
    __nv_bfloat16 *p_bW0, *p_bW1, *p_bWq, *p_bWk, *p_bWv, *p_bF1, *p_bF2;
    float *p_eW2, *p_rW1, *p_Khat, *p_h, *p_hW0, *p_qh, *p_x;
    cudaGetSymbolAddress((void**)&p_embeH, g_embeH);
    cudaGetSymbolAddress((void**)&p_bW2h,  g_bW2h);
    cudaGetSymbolAddress((void**)&p_eW2,   g_eW2);
    cudaGetSymbolAddress((void**)&p_embr2, g_embr2);
    cudaGetSymbolAddress((void**)&p_embq2, g_embq2);
    cudaGetSymbolAddress((void**)&p_h2,    g_h2);
    cudaGetSymbolAddress((void**)&p_ctx2,  g_ctx2);
    cudaGetSymbolAddress((void**)&p_ff2,   g_ff2);
    cudaGetSymbolAddress((void**)&p_bW0,   g_bW0);
    cudaGetSymbolAddress((void**)&p_bW1,   g_bW1);
    cudaGetSymbolAddress((void**)&p_bWq,   g_bWq);
    cudaGetSymbolAddress((void**)&p_bWk,   g_bWk);
    cudaGetSymbolAddress((void**)&p_bWv,   g_bWv);
    cudaGetSymbolAddress((void**)&p_bF1,   g_bF1);
    cudaGetSymbolAddress((void**)&p_bF2,   g_bF2);
    cudaGetSymbolAddress((void**)&p_rW1,   g_rW1);
    cudaGetSymbolAddress((void**)&p_Khat,  g_Khat);
    cudaGetSymbolAddress((void**)&p_h,     g_h);
    cudaGetSymbolAddress((void**)&p_hW0,   g_hW0);
    cudaGetSymbolAddress((void**)&p_qh,    g_qh);
    cudaGetSymbolAddress((void**)&p_x,     g_x);

    const int SM128 = 512 + 4 * (256 * 64);  // 66048
    const int SM64  = 512 + 4 * (192 * 64);  // 49664
    cudaFuncSetAttribute(gemm_h<128, 3, 0>, cudaFuncAttributeMaxDynamicSharedMemorySize, SM128);
    cudaFuncSetAttribute(gemm_h<64, 3, 0>,  cudaFuncAttributeMaxDynamicSharedMemorySize, SM64);
    cudaFuncSetAttribute(gemm_h<128, 1, 1>, cudaFuncAttributeMaxDynamicSharedMemorySize, SM128);

    int writeq = (out_size >= 2 * BB * DD) ? 1 : 0;
    // launches 1-5
    init_k<<<BB, 128>>>(e1, qidx, emb_e, emb_r, p_h, p_h2, p_embq2, out + (size_t)BB * DD, writeq);
    convA_h<<<EE, 128>>>(emb_e, p_embeH);
    convA_k<<<RR, 128>>>(emb_r, p_embr2);
    convW_h<<<(512 * 512 + 255) / 256, 256>>>(msg_W + 1024 * 512, 512, 512, p_bW2h);
    convW_k<<<(512 * 512 + 255) / 256, 256>>>(msg_W + 512 * 512, 512, 64, 512, 512, p_bW1);
    // launch 6: the big one (profiled by ncu -s 5 -c 1)
    // eW2 = emb_e @ W2 + msg_b   (fp16 single)
    gemm_h<128, 1, 1><<<dim3(4, (EE + 127) / 128), 256, SM128>>>(
        (const __nv_bfloat16*)p_embeH, 512, 0, nullptr, EE,
        (const __nv_bfloat16*)p_bW2h, 0, 512,
        msg_b, p_eW2, 512, 0, 0, 0, 0, nullptr, 0, 0, 0);

    convW_k<<<(512 * 512 + 255) / 256, 256>>>(msg_W, 512, 64, 512, 512, p_bW0);
    for (int l = 0; l < LL; l++) {
        convW_k<<<(512 * 512 + 255) / 256, 256>>>(Wq + (size_t)l * 512 * 512, 64, 32768, 512, 512, p_bWq + (size_t)l * 512 * 1024);
        convW_k<<<(512 * 512 + 255) / 256, 256>>>(Wk + (size_t)l * 512 * 512, 64, 32768, 512, 512, p_bWk + (size_t)l * 512 * 1024);
        convW_k<<<(512 * 512 + 255) / 256, 256>>>(Wv + (size_t)l * 512 * 512, 64, 32768, 512, 512, p_bWv + (size_t)l * 512 * 1024);
        convW_k<<<(512 * 2048 + 255) / 256, 256>>>(ffW1 + (size_t)l * 512 * 2048, 2048, 64, 512, 2048, p_bF1 + (size_t)l * 2048 * 1024);
        convW_k<<<(2048 * 512 + 255) / 256, 256>>>(ffW2 + (size_t)l * 2048 * 512, 512, 64, 2048, 512, p_bF2 + (size_t)l * 512 * 4096);
    }

    // rW1 = emb_r @ W1  (no bias; msg_b folded into eW2)
    gemm_h<128, 3, 0><<<dim3(4, 4), 256, SM128>>>(
        p_embr2, 1024, 0, nullptr, RR, p_bW1, 0, 512,
        nullptr, p_rW1, 512, 0, 0, 0, 0, nullptr, 0, 0, 0);
    // Khat[l] = emb_r @ Wk[l](stacked) + bk[l]
    for (int l = 0; l < LL; l++)
        gemm_h<128, 3, 0><<<dim3(4, 4), 256, SM128>>>(
            p_embr2, 1024, 0, nullptr, RR,
            p_bWk + (size_t)l * 512 * 1024, 0, 512,
            bk + l * 512, p_Khat + (size_t)l * RR * 512, 512, 0, 0, 0, 0, nullptr, 0, 0, 0);

    for (int l = 0; l < LL; l++) {
        // hW0 = h @ W0
        gemm_h<128, 3, 0><<<dim3(4, 16), 256, SM128>>>(
            p_h2, 1024, 0, nullptr, BB, p_bW0, 0, 512,
            nullptr, p_hW0, 512, 0, 0, 0, 0, nullptr, 0, 0, 0);
        // qh = embq @ Wq[l](stacked) + bq[l]
        gemm_h<128, 3, 0><<<dim3(4, 16), 256, SM128>>>(
            p_embq2, 1024, 0, nullptr, BB,
            p_bWq + (size_t)l * 512 * 1024, 0, 512,
            bq + l * 512, p_qh, 512, 0, 0, 0, 0, nullptr, 0, 0, 0);
        attn_k<<<BB, 256>>>(p_qh, p_Khat + (size_t)l * RR * 512, nbr_r, nbr_e, masks,
                            p_hW0, p_eW2, p_rW1, p_ctx2);
        // x = ctx @ Wv[l] + bv[l]  (z = head)
        gemm_h<64, 3, 0><<<dim3(1, 16, 8), 256, SM64>>>(
            p_ctx2, 8192, 1024, nullptr, BB,
            p_bWv + (size_t)l * 512 * 1024, 65536, 512,
            bv + l * 512, p_x, 512, 64, 0, 0, 0, nullptr, 0, 0, 0);
        ln_k<<<BB, 128>>>(p_h, p_x, nullptr, ln1g + l * 512, ln1b + l * 512, p_h2);
        // ff2 = split(relu(h @ F1 + b1))
        gemm_h<128, 3, 0><<<dim3(16, 16), 256, SM128>>>(
            p_h2, 1024, 0, nullptr, BB,
            p_bF1 + (size_t)l * 2048 * 1024, 0, 512,
            ffb1 + l * 2048, nullptr, 0, 0, 0, 0, 0, p_ff2, 4096, 2048, 1);
        // x0/x1 = split-K halves of ff @ F2 (+ b2 on z=0)
        gemm_h<128, 3, 0><<<dim3(4, 16, 2), 256, SM128>>>(
            p_ff2, 4096, 0, nullptr, BB,
            p_bF2 + (size_t)l * 512 * 4096, 0, 2048,
            ffb2 + l * 512, p_x, 512, 0, (long long)BB * 512, 1, 96, nullptr, 0, 0, 0);
        ln_k<<<BB, 128>>>(p_h, p_x, p_x + (size_t)BB * 512, ln2g + l * 512, ln2b + l * 512, p_h2);
    }

    copy_k<<<(BB * DD) / 256, 256>>>(out, p_h);
}

// round 6
// speedup vs baseline: 3.1814x; 1.2805x over previous
#include <cuda_runtime.h>
#include <cuda_bf16.h>
#include <cuda_fp16.h>
#include <cstdint>

#define BB 2048
#define NN 64
#define DD 512
#define HH 8
#define LL 3
#define FFD 2048
#define RR 400
#define EE 100000

// ---------------- device scratch ----------------
__device__ __align__(256) __half        g_embeH[EE * 512];     // emb_e fp16
__device__ __align__(256) __half        g_eW2H[EE * 512];      // emb_e @ W2 + msg_b (fp16)
__device__ __align__(256) __half        g_bW2h[512 * 512];
__device__ __align__(256) __half        g_bW0h[512 * 512];
__device__ __align__(256) __half        g_bWvh[LL * 512 * 512];
__device__ __align__(256) __half        g_bF1h[LL * 2048 * 512];
__device__ __align__(256) __half        g_bF2h[LL * 512 * 2048];
__device__ __align__(256) __half        g_hH[BB * 512];        // fp16 copy of h
__device__ __align__(256) __half        g_ctxH[BB * HH * 512];
__device__ __align__(256) __half        g_ffH[BB * 2048];
__device__ __align__(256) __nv_bfloat16 g_embr2[RR * 1024];
__device__ __align__(256) __nv_bfloat16 g_embq2[BB * 1024];
__device__ __align__(256) __nv_bfloat16 g_bW1[512 * 1024];
__device__ __align__(256) __nv_bfloat16 g_bWq[LL * 512 * 1024];
__device__ __align__(256) __nv_bfloat16 g_bWk[LL * 512 * 1024];
__device__ __align__(256) float g_rW1[RR * 512];
__device__ __align__(256) float g_Khat[LL * RR * 512];
__device__ __align__(256) float g_h[BB * 512];
__device__ __align__(256) float g_hW0[BB * 512];
__device__ __align__(256) float g_qh[BB * 512];
__device__ __align__(256) float g_x[2 * BB * 512];

// ---------------- helpers ----------------
__device__ __forceinline__ uint32_t s2u(const void* p) {
    uint32_t a;
    asm("{ .reg .u64 t; cvta.to.shared.u64 t, %1; cvt.u32.u64 %0, t; }" : "=r"(a) : "l"(p));
    return a;
}
__device__ __forceinline__ void cp16(uint32_t d, const void* s) {
    asm volatile("cp.async.cg.shared.global [%0], [%1], 16;" :: "r"(d), "l"(s));
}
__device__ __forceinline__ void cp_commit() { asm volatile("cp.async.commit_group;" ::: "memory"); }
template<int G> __device__ __forceinline__ void cp_wait() {
    asm volatile("cp.async.wait_group %0;" :: "n"(G) : "memory");
}
__device__ __forceinline__ void ldm4(uint32_t& r0, uint32_t& r1, uint32_t& r2, uint32_t& r3, uint32_t a) {
    asm volatile("ldmatrix.sync.aligned.m8n8.x4.shared.b16 {%0,%1,%2,%3}, [%4];"
        : "=r"(r0), "=r"(r1), "=r"(r2), "=r"(r3) : "r"(a));
}
__device__ __forceinline__ void mma_bf16(float* c, const uint32_t* a, const uint32_t* b) {
    asm volatile(
        "mma.sync.aligned.m16n8k16.row.col.f32.bf16.bf16.f32 "
        "{%0,%1,%2,%3}, {%4,%5,%6,%7}, {%8,%9}, {%0,%1,%2,%3};"
        : "+f"(c[0]), "+f"(c[1]), "+f"(c[2]), "+f"(c[3])
        : "r"(a[0]), "r"(a[1]), "r"(a[2]), "r"(a[3]), "r"(b[0]), "r"(b[1]));
}
__device__ __forceinline__ void mma_f16(float* c, const uint32_t* a, const uint32_t* b) {
    asm volatile(
        "mma.sync.aligned.m16n8k16.row.col.f32.f16.f16.f32 "
        "{%0,%1,%2,%3}, {%4,%5,%6,%7}, {%8,%9}, {%0,%1,%2,%3};"
        : "+f"(c[0]), "+f"(c[1]), "+f"(c[2]), "+f"(c[3])
        : "r"(a[0]), "r"(a[1]), "r"(a[2]), "r"(a[3]), "r"(b[0]), "r"(b[1]));
}
__device__ __forceinline__ void bf16pair(float x, __nv_bfloat16& h, __nv_bfloat16& l) {
    h = __float2bfloat16_rn(x);
    l = __float2bfloat16_rn(x - __bfloat162float(h));
}
// 16B-chunk swizzle within 64B rows: conflict-free ldmatrix
__device__ __forceinline__ int swz4(int row, int c) {
    int s = row & 7;
    return ((c + (s >> 2)) ^ (s & 3)) & 3;
}

// ---------------- HMMA GEMM ----------------
// NSEG=3: split-bf16 hi/lo (A,B have 2K 16-bit elems per row). NSEG=1: single (fp16 if DT=1).
// OUTH=1: C is __half*, write half2. kz: split-K over blockIdx.z, C += z*czoff, bias z==0 only.
template<int BN, int NSEG, int DT, int OUTH>
__global__ void __launch_bounds__(256) gemm_h(
    const __nv_bfloat16* __restrict__ A, int a_ld, int za,
    const int* __restrict__ gidx, int M,
    const __nv_bfloat16* __restrict__ B2, int zb, int K,
    const float* __restrict__ bias,
    float* __restrict__ C, int ldc, int zn, long long czoff, int kz, int kspan,
    __nv_bfloat16* __restrict__ Cbf, int cbf_ld, int cbf_half,
    int act)
{
    constexpr int WARPS_N = BN / 32;
    constexpr int WARPS_M = 8 / WARPS_N;
    constexpr int WM = 128 / WARPS_M;
    constexpr int MAT_M = WM / 16;
    constexpr int STAGE = (128 + BN) * 64;
    constexpr int UNITS = (128 + BN) * 4;

    extern __shared__ __align__(1024) char smem[];
    int* s_idx = (int*)smem;
    const uint32_t sb = s2u(smem);
    const int tid = threadIdx.x, w = tid >> 5, lane = tid & 31;
    const int wm = w / WARPS_N, wn = w % WARPS_N;
    const int gm0 = blockIdx.y * 128;
    const int bn0 = blockIdx.x * BN;
    const int n0g = bn0 + (int)blockIdx.z * zn;
    const size_t zoffA = (size_t)blockIdx.z * za;
    const size_t zoffB = (size_t)blockIdx.z * zb;
    const int brs = (NSEG == 3) ? 2 * K : K;

    if (kz && blockIdx.z > 0) bias = nullptr;
    if (kz) C += (size_t)blockIdx.z * czoff;

    if (tid < 128) {
        int gr = gm0 + tid;
        if (gr >= M) gr = M - 1;
        s_idx[tid] = gidx ? gidx[gr] : gr;
    }
    __syncthreads();

    const int Kq = K >> 5;
    const int NCH = NSEG * Kq;
    const int kbeg = kz ? (int)blockIdx.z * kspan : 0;
    const int kcnt = kz ? kspan : NCH;

    auto load_chunk = [&](int c) {
        int s = c & 3;
        int seg = (NSEG == 3) ? c / Kq : 0;
        int kk = c - seg * Kq;
        int aoff = ((seg == 2) ? K : 0) + kk * 32;
        int boff = ((seg == 1) ? K : 0) + kk * 32;
        uint32_t st = sb + 512 + s * STAGE;
#pragma unroll
        for (int it = 0; it < UNITS / 256; it++) {
            int u = tid + it * 256;
            if (u < 512) {
                int r = u >> 2, c16 = u & 3;
                cp16(st + r * 64 + swz4(r, c16) * 16,
                     A + (size_t)s_idx[r] * a_ld + zoffA + aoff + c16 * 8);
            } else {
                int v = u - 512;
                int n = v >> 2, c16 = v & 3;
                cp16(st + 8192 + n * 64 + swz4(n, c16) * 16,
                     B2 + zoffB + (size_t)(bn0 + n) * brs + boff + c16 * 8);
            }
        }
        cp_commit();
    };

    float acc[MAT_M][4][4];
#pragma unroll
    for (int i = 0; i < MAT_M; i++)
#pragma unroll
        for (int j = 0; j < 4; j++)
#pragma unroll
            for (int q = 0; q < 4; q++) acc[i][j][q] = 0.f;

    load_chunk(kbeg);
    load_chunk(kbeg + 1);
    load_chunk(kbeg + 2);

    const int r8 = lane & 7, sel = lane >> 3;

    for (int cc = 0; cc < kcnt; cc++) {
        int c = kbeg + cc;
        cp_wait<2>();
        __syncthreads();
        uint32_t stA = sb + 512 + (c & 3) * STAGE;
        uint32_t stB = stA + 8192;
#pragma unroll
        for (int kt = 0; kt < 2; kt++) {
            uint32_t a[MAT_M][4];
#pragma unroll
            for (int i = 0; i < MAT_M; i++) {
                int ar = wm * WM + i * 16 + r8 + (sel & 1) * 8;
                int ac = kt * 2 + (sel >> 1);
                ldm4(a[i][0], a[i][1], a[i][2], a[i][3],
                     stA + ar * 64 + swz4(ar, ac) * 16);
            }
            uint32_t b[4][2];
#pragma unroll
            for (int p = 0; p < 2; p++) {
                int br = wn * 32 + p * 16 + r8 + (sel >> 1) * 8;
                int bc = kt * 2 + (sel & 1);
                uint32_t t0, t1, t2, t3;
                ldm4(t0, t1, t2, t3, stB + br * 64 + swz4(br, bc) * 16);
                b[2 * p][0] = t0; b[2 * p][1] = t1;
                b[2 * p + 1][0] = t2; b[2 * p + 1][1] = t3;
            }
#pragma unroll
            for (int i = 0; i < MAT_M; i++)
#pragma unroll
                for (int j = 0; j < 4; j++) {
                    if (DT == 0) mma_bf16(acc[i][j], a[i], b[j]);
                    else         mma_f16(acc[i][j], a[i], b[j]);
                }
        }
        if (cc + 3 < kcnt) load_chunk(c + 3);
        else cp_commit();
    }

    // epilogue
    const int g = lane >> 2, tig = lane & 3;
#pragma unroll
    for (int i = 0; i < MAT_M; i++) {
#pragma unroll
        for (int half = 0; half < 2; half++) {
            int m = gm0 + wm * WM + i * 16 + g + half * 8;
            if (m < M) {
#pragma unroll
                for (int j = 0; j < 4; j++) {
                    int nc = n0g + wn * 32 + j * 8 + tig * 2;
                    float v0 = acc[i][j][half * 2 + 0];
                    float v1 = acc[i][j][half * 2 + 1];
                    if (bias) { v0 += bias[nc]; v1 += bias[nc + 1]; }
                    if (act)  { v0 = fmaxf(v0, 0.f); v1 = fmaxf(v1, 0.f); }
                    if (OUTH) {
                        __half2 o = __floats2half2_rn(v0, v1);
                        *(__half2*)&((__half*)C)[(size_t)m * ldc + nc] = o;
                    } else if (C) {
                        float2 o; o.x = v0; o.y = v1;
                        *(float2*)&C[(size_t)m * ldc + nc] = o;
                    }
                    if (Cbf) {
                        __nv_bfloat16 h0, l0, h1, l1;
                        bf16pair(v0, h0, l0);
                        bf16pair(v1, h1, l1);
                        __nv_bfloat162 ph, pl;
                        ph.x = h0; ph.y = h1; pl.x = l0; pl.y = l1;
                        *(__nv_bfloat162*)&Cbf[(size_t)m * cbf_ld + nc] = ph;
                        *(__nv_bfloat162*)&Cbf[(size_t)m * cbf_ld + cbf_half + nc] = pl;
                    }
                }
            }
        }
    }
}

// ---------------- conversions ----------------
__global__ void __launch_bounds__(256) convW_k(
    const float* __restrict__ W, int str_k, int str_h, int K, int N,
    __nv_bfloat16* __restrict__ B2)
{
    int idx = blockIdx.x * 256 + threadIdx.x;
    if (idx >= K * N) return;
    int n = idx / K, k = idx - n * K;
    float x = W[(size_t)k * str_k + (size_t)(n >> 6) * str_h + (n & 63)];
    __nv_bfloat16 h, l; bf16pair(x, h, l);
    B2[(size_t)n * 2 * K + k] = h;
    B2[(size_t)n * 2 * K + K + k] = l;
}

__global__ void __launch_bounds__(256) convW_h(
    const float* __restrict__ W, int str_k, int str_h, int K, int N,
    __half* __restrict__ B2)
{
    int idx = blockIdx.x * 256 + threadIdx.x;
    if (idx >= K * N) return;
    int n = idx / K, k = idx - n * K;
    float x = W[(size_t)k * str_k + (size_t)(n >> 6) * str_h + (n & 63)];
    B2[(size_t)n * K + k] = __float2half_rn(x);
}

__global__ void __launch_bounds__(128) convA_k(
    const float* __restrict__ src, __nv_bfloat16* __restrict__ dst)
{
    int row = blockIdx.x;
    const float* s = src + (size_t)row * 512;
    __nv_bfloat16* d = dst + (size_t)row * 1024;
    for (int k = threadIdx.x; k < 512; k += 128) {
        __nv_bfloat16 h, l; bf16pair(s[k], h, l);
        d[k] = h; d[512 + k] = l;
    }
}

__global__ void __launch_bounds__(128) convA_h(
    const float* __restrict__ src, __half* __restrict__ dst)
{
    size_t i = (size_t)blockIdx.x * 512 + threadIdx.x;
#pragma unroll
    for (int t = 0; t < 4; t++)
        dst[i + t * 128] = __float2half_rn(src[i + t * 128]);
}

// ---------------- fused attention ----------------
__global__ void __launch_bounds__(256) attn_k(
    const float* __restrict__ qh, const float* __restrict__ Khat,  // [R][512] this layer
    const int* __restrict__ nbr_r, const int* __restrict__ nbr_e,
    const float* __restrict__ masks,
    const float* __restrict__ hW0, const __half* __restrict__ eW2,
    const float* __restrict__ rW1,
    __half* __restrict__ ctxH)
{
    const int b = blockIdx.x;
    const int tid = threadIdx.x;
    const int lane = tid & 31, w = tid >> 5;

    __shared__ float s_q[512];
    __shared__ float s_attn[HH * 64];
    __shared__ int   s_nbr[NN], s_nbe[NN];

    s_q[tid]       = qh[(size_t)b * 512 + tid];
    s_q[tid + 256] = qh[(size_t)b * 512 + tid + 256];
    if (tid < NN) { s_nbr[tid] = nbr_r[b * NN + tid]; s_nbe[tid] = nbr_e[b * NN + tid]; }
    __syncthreads();

    {
        float q0 = s_q[w * 64 + lane], q1 = s_q[w * 64 + lane + 32];
        for (int n = 0; n < NN; n++) {
            int j = s_nbr[n];
            const float* kr = Khat + (size_t)j * 512 + w * 64;
            float p = q0 * kr[lane] + q1 * kr[lane + 32];
#pragma unroll
            for (int o = 16; o; o >>= 1) p += __shfl_xor_sync(0xffffffffu, p, o);
            if (lane == 0)
                s_attn[w * 64 + n] = p * 0.125f - 1e31f * (1.0f - masks[b * NN + n]);
        }
    }
    __syncwarp();
    {
        float s0 = s_attn[w * 64 + lane], s1 = s_attn[w * 64 + lane + 32];
        float m = fmaxf(s0, s1);
#pragma unroll
        for (int o = 16; o; o >>= 1) m = fmaxf(m, __shfl_xor_sync(0xffffffffu, m, o));
        float e0 = expf(s0 - m), e1 = expf(s1 - m);
        float sum = e0 + e1;
#pragma unroll
        for (int o = 16; o; o >>= 1) sum += __shfl_xor_sync(0xffffffffu, sum, o);
        float inv = 1.f / sum;
        s_attn[w * 64 + lane]      = e0 * inv;
        s_attn[w * 64 + lane + 32] = e1 * inv;
    }
    __syncthreads();

    const float hw0a = hW0[(size_t)b * 512 + tid];
    const float hw0b = hW0[(size_t)b * 512 + tid + 256];
    float acc[HH][2];
#pragma unroll
    for (int hh = 0; hh < HH; hh++) { acc[hh][0] = 0.f; acc[hh][1] = 0.f; }

#pragma unroll 2
    for (int n = 0; n < NN; n++) {
        const __half* ep = eW2 + (size_t)s_nbe[n] * 512;
        const float* rp = rW1 + (size_t)s_nbr[n] * 512;
        float v0 = hw0a + __half2float(ep[tid]) + rp[tid];
        float v1 = hw0b + __half2float(ep[tid + 256]) + rp[tid + 256];
        v0 = (v0 > 0.f) ? v0 : 0.01f * v0;
        v1 = (v1 > 0.f) ? v1 : 0.01f * v1;
#pragma unroll
        for (int hh = 0; hh < HH; hh++) {
            float a = s_attn[hh * 64 + n];
            acc[hh][0] += a * v0;
            acc[hh][1] += a * v1;
        }
    }
#pragma unroll
    for (int hh = 0; hh < HH; hh++) {
        __half* cb = ctxH + ((size_t)b * HH + hh) * 512;
        cb[tid]       = __float2half_rn(acc[hh][0]);
        cb[tid + 256] = __float2half_rn(acc[hh][1]);
    }
}

// ---------------- layernorm (+ optional second x, + fp16 out) ----------------
__global__ void __launch_bounds__(128) ln_k(
    float* __restrict__ h, const float* __restrict__ x, const float* __restrict__ x2,
    const float* __restrict__ gamma, const float* __restrict__ beta,
    __half* __restrict__ hH)
{
    const int b = blockIdx.x, tid = threadIdx.x;
    __shared__ float sred[8];
    float4 hv = ((const float4*)(h + (size_t)b * 512))[tid];
    float4 xv = ((const float4*)(x + (size_t)b * 512))[tid];
    float v0 = hv.x + xv.x, v1 = hv.y + xv.y, v2 = hv.z + xv.z, v3 = hv.w + xv.w;
    if (x2) {
        float4 x2v = ((const float4*)(x2 + (size_t)b * 512))[tid];
        v0 += x2v.x; v1 += x2v.y; v2 += x2v.z; v3 += x2v.w;
    }

    float s = v0 + v1 + v2 + v3;
#pragma unroll
    for (int o = 16; o; o >>= 1) s += __shfl_xor_sync(0xffffffffu, s, o);
    if ((tid & 31) == 0) sred[tid >> 5] = s;
    __syncthreads();
    float mean = (sred[0] + sred[1] + sred[2] + sred[3]) * (1.f / 512.f);

    v0 -= mean; v1 -= mean; v2 -= mean; v3 -= mean;
    float sq = v0 * v0 + v1 * v1 + v2 * v2 + v3 * v3;
#pragma unroll
    for (int o = 16; o; o >>= 1) sq += __shfl_xor_sync(0xffffffffu, sq, o);
    if ((tid & 31) == 0) sred[4 + (tid >> 5)] = sq;
    __syncthreads();
    float var = (sred[4] + sred[5] + sred[6] + sred[7]) * (1.f / 512.f);
    float rstd = rsqrtf(var + 1e-5f);

    float4 g = ((const float4*)gamma)[tid];
    float4 be = ((const float4*)beta)[tid];
    float o0 = v0 * rstd * g.x + be.x;
    float o1 = v1 * rstd * g.y + be.y;
    float o2 = v2 * rstd * g.z + be.z;
    float o3 = v3 * rstd * g.w + be.w;
    float4 o; o.x = o0; o.y = o1; o.z = o2; o.w = o3;
    ((float4*)(h + (size_t)b * 512))[tid] = o;

    __half2 p0 = __floats2half2_rn(o0, o1);
    __half2 p1 = __floats2half2_rn(o2, o3);
    __half2* d = (__half2*)(hH + (size_t)b * 512 + tid * 4);
    d[0] = p0; d[1] = p1;
}

// ---------------- init ----------------
__global__ void __launch_bounds__(128) init_k(
    const int* __restrict__ e1, const int* __restrict__ qi,
    const float* __restrict__ emb_e, const float* __restrict__ emb_r,
    float* __restrict__ h, __half* __restrict__ hH,
    __nv_bfloat16* __restrict__ embq2,
    float* __restrict__ outq, int writeq)
{
    const int b = blockIdx.x, t = threadIdx.x;
    const float* se = emb_e + (size_t)e1[b] * 512;
    const float* sr = emb_r + (size_t)qi[b] * 512;
    for (int j = t; j < 512; j += 128) {
        float hv = se[j];
        h[(size_t)b * 512 + j] = hv;
        hH[(size_t)b * 512 + j] = __float2half_rn(hv);
        float q = sr[j];
        __nv_bfloat16 hh, ll;
        bf16pair(q, hh, ll);
        embq2[(size_t)b * 1024 + j] = hh; embq2[(size_t)b * 1024 + 512 + j] = ll;
        if (writeq) outq[(size_t)b * 512 + j] = q;
    }
}

__global__ void copy_k(float* __restrict__ out, const float* __restrict__ in)
{
    int i = blockIdx.x * 256 + threadIdx.x;
    out[i] = in[i];
}

// ---------------- launch ----------------
extern "C" void kernel_launch(void* const* d_in, const int* in_sizes, int n_in,
                              void* d_out, int out_size)
{
    const int*   e1    = (const int*)d_in[0];
    const int*   qidx  = (const int*)d_in[1];
    const int*   nbr_r = (const int*)d_in[2];
    const int*   nbr_e = (const int*)d_in[3];
    const float* masks = (const float*)d_in[4];
    const float* emb_e = (const float*)d_in[5];
    const float* emb_r = (const float*)d_in[6];
    const float* msg_W = (const float*)d_in[7];
    const float* msg_b = (const float*)d_in[8];
    const float* Wq    = (const float*)d_in[9];
    const float* bq    = (const float*)d_in[10];
    const float* Wk    = (const float*)d_in[11];
    const float* bk    = (const float*)d_in[12];
    const float* Wv    = (const float*)d_in[13];
    const float* bv    = (const float*)d_in[14];
    const float* ffW1  = (const float*)d_in[15];
    const float* ffb1  = (const float*)d_in[16];
    const float* ffW2  = (const float*)d_in[17];
    const float* ffb2  = (const float*)d_in[18];
    const float* ln1g  = (const float*)d_in[19];
    const float* ln1b  = (const float*)d_in[20];
    const float* ln2g  = (const float*)d_in[21];
    const float* ln2b  = (const float*)d_in[22];
    float* out = (float*)d_out;

    __half *p_embeH, *p_eW2H, *p_bW2h, *p_bW0h, *p_bWvh, *p_bF1h, *p_bF2h, *p_hH, *p_ctxH, *p_ffH;
    __nv_bfloat16 *p_embr2, *p_embq2, *p_bW1, *p_bWq, *p_bWk;
    float *p_rW1, *p_Khat, *p_h, *p_hW0, *p_qh, *p_x;
    cudaGetSymbolAddress((void**)&p_embeH, g_embeH);
    cudaGetSymbolAddress((void**)&p_eW2H,  g_eW2H);
    cudaGetSymbolAddress((void**)&p_bW2h,  g_bW2h);
    cudaGetSymbolAddress((void**)&p_bW0h,  g_bW0h);
    cudaGetSymbolAddress((void**)&p_bWvh,  g_bWvh);
    cudaGetSymbolAddress((void**)&p_bF1h,  g_bF1h);
    cudaGetSymbolAddress((void**)&p_bF2h,  g_bF2h);
    cudaGetSymbolAddress((void**)&p_hH,    g_hH);
    cudaGetSymbolAddress((void**)&p_ctxH,  g_ctxH);
    cudaGetSymbolAddress((void**)&p_ffH,   g_ffH);
    cudaGetSymbolAddress((void**)&p_embr2, g_embr2);
    cudaGetSymbolAddress((void**)&p_embq2, g_embq2);
    cudaGetSymbolAddress((void**)&p_bW1,   g_bW1);
    cudaGetSymbolAddress((void**)&p_bWq,   g_bWq);
    cudaGetSymbolAddress((void**)&p_bWk,   g_bWk);
    cudaGetSymbolAddress((void**)&p_rW1,   g_rW1);
    cudaGetSymbolAddress((void**)&p_Khat,  g_Khat);
    cudaGetSymbolAddress((void**)&p_h,     g_h);
    cudaGetSymbolAddress((void**)&p_hW0,   g_hW0);
    cudaGetSymbolAddress((void**)&p_qh,    g_qh);
    cudaGetSymbolAddress((void**)&p_x,     g_x);

    const int SM128 = 512 + 4 * (256 * 64);  // 66048
    const int SM64  = 512 + 4 * (192 * 64);  // 49664
    cudaFuncSetAttribute((gemm_h<128, 3, 0, 0>), cudaFuncAttributeMaxDynamicSharedMemorySize, SM128);
    cudaFuncSetAttribute((gemm_h<128, 1, 1, 0>), cudaFuncAttributeMaxDynamicSharedMemorySize, SM128);
    cudaFuncSetAttribute((gemm_h<128, 1, 1, 1>), cudaFuncAttributeMaxDynamicSharedMemorySize, SM128);
    cudaFuncSetAttribute((gemm_h<64, 1, 1, 0>),  cudaFuncAttributeMaxDynamicSharedMemorySize, SM64);

    int writeq = (out_size >= 2 * BB * DD) ? 1 : 0;
    // launches 1-3
    init_k<<<BB, 128>>>(e1, qidx, emb_e, emb_r, p_h, p_hH, p_embq2, out + (size_t)BB * DD, writeq);
    convA_h<<<EE, 128>>>(emb_e, p_embeH);
    convW_h<<<1024, 256>>>(msg_W + 1024 * 512, 512, 64, 512, 512, p_bW2h);
    // launch 4: eW2 = emb_e @ W2 + msg_b (fp16, profiled slot)
    gemm_h<128, 1, 1, 1><<<dim3(4, (EE + 127) / 128), 256, SM128>>>(
        (const __nv_bfloat16*)p_embeH, 512, 0, nullptr, EE,
        (const __nv_bfloat16*)p_bW2h, 0, 512,
        msg_b, (float*)p_eW2H, 512, 0, 0, 0, 0, nullptr, 0, 0, 0);

    // remaining conversions
    convA_k<<<RR, 128>>>(emb_r, p_embr2);
    convW_k<<<1024, 256>>>(msg_W + 512 * 512, 512, 64, 512, 512, p_bW1);
    convW_h<<<1024, 256>>>(msg_W, 512, 64, 512, 512, p_bW0h);
    for (int l = 0; l < LL; l++) {
        convW_k<<<1024, 256>>>(Wq + (size_t)l * 512 * 512, 64, 32768, 512, 512, p_bWq + (size_t)l * 512 * 1024);
        convW_k<<<1024, 256>>>(Wk + (size_t)l * 512 * 512, 64, 32768, 512, 512, p_bWk + (size_t)l * 512 * 1024);
        convW_h<<<1024, 256>>>(Wv + (size_t)l * 512 * 512, 64, 32768, 512, 512, p_bWvh + (size_t)l * 512 * 512);
        convW_h<<<4096, 256>>>(ffW1 + (size_t)l * 512 * 2048, 2048, 64, 512, 2048, p_bF1h + (size_t)l * 2048 * 512);
        convW_h<<<4096, 256>>>(ffW2 + (size_t)l * 2048 * 512, 512, 64, 2048, 512, p_bF2h + (size_t)l * 512 * 2048);
    }

    // rW1 = emb_r @ W1 (split bf16; msg_b folded into eW2)
    gemm_h<128, 3, 0, 0><<<dim3(4, 4), 256, SM128>>>(
        p_embr2, 1024, 0, nullptr, RR, p_bW1, 0, 512,
        nullptr, p_rW1, 512, 0, 0, 0, 0, nullptr, 0, 0, 0);
    // Khat[l] = emb_r @ Wk[l](stacked) + bk[l]
    for (int l = 0; l < LL; l++)
        gemm_h<128, 3, 0, 0><<<dim3(4, 4), 256, SM128>>>(
            p_embr2, 1024, 0, nullptr, RR,
            p_bWk + (size_t)l * 512 * 1024, 0, 512,
            bk + l * 512, p_Khat + (size_t)l * RR * 512, 512, 0, 0, 0, 0, nullptr, 0, 0, 0);

    for (int l = 0; l < LL; l++) {
        // hW0 = h @ W0 (fp16)
        gemm_h<128, 1, 1, 0><<<dim3(4, 16), 256, SM128>>>(
            (const __nv_bfloat16*)p_hH, 512, 0, nullptr, BB,
            (const __nv_bfloat16*)p_bW0h, 0, 512,
            nullptr, p_hW0, 512, 0, 0, 0, 0, nullptr, 0, 0, 0);
        // qh = embq @ Wq[l](stacked) + bq[l] (split bf16 — exact score path)
        gemm_h<128, 3, 0, 0><<<dim3(4, 16), 256, SM128>>>(
            p_embq2, 1024, 0, nullptr, BB,
            p_bWq + (size_t)l * 512 * 1024, 0, 512,
            bq + l * 512, p_qh, 512, 0, 0, 0, 0, nullptr, 0, 0, 0);
        attn_k<<<BB, 256>>>(p_qh, p_Khat + (size_t)l * RR * 512, nbr_r, nbr_e, masks,
                            p_hW0, p_eW2H, p_rW1, p_ctxH);
        // x = ctx @ Wv[l] + bv[l] (fp16, z = head)
        gemm_h<64, 1, 1, 0><<<dim3(1, 16, 8), 256, SM64>>>(
            (const __nv_bfloat16*)p_ctxH, 4096, 512, nullptr, BB,
            (const __nv_bfloat16*)(p_bWvh + (size_t)l * 512 * 512), 32768, 512,
            bv + l * 512, p_x, 512, 64, 0, 0, 0, nullptr, 0, 0, 0);
        ln_k<<<BB, 128>>>(p_h, p_x, nullptr, ln1g + l * 512, ln1b + l * 512, p_hH);
        // ffH = fp16(relu(h @ F1 + b1))
        gemm_h<128, 1, 1, 1><<<dim3(16, 16), 256, SM128>>>(
            (const __nv_bfloat16*)p_hH, 512, 0, nullptr, BB,
            (const __nv_bfloat16*)(p_bF1h + (size_t)l * 2048 * 512), 0, 512,
            ffb1 + l * 2048, (float*)p_ffH, 2048, 0, 0, 0, 0, nullptr, 0, 0, 1);
        // x0/x1 = split-K halves of ff @ F2 (+ b2 on z=0)
        gemm_h<128, 1, 1, 0><<<dim3(4, 16, 2), 256, SM128>>>(
            (const __nv_bfloat16*)p_ffH, 2048, 0, nullptr, BB,
            (const __nv_bfloat16*)(p_bF2h + (size_t)l * 512 * 2048), 0, 2048,
            ffb2 + l * 512, p_x, 512, 0, (long long)BB * 512, 1, 32, nullptr, 0, 0, 0);
        ln_k<<<BB, 128>>>(p_h, p_x, p_x + (size_t)BB * 512, ln2g + l * 512, ln2b + l * 512, p_hH);
    }

    copy_k<<<(BB * DD) / 256, 256>>>(out, p_h);
}

// round 8
// speedup vs baseline: 3.8397x; 1.2069x over previous
#include <cuda_runtime.h>
#include <cuda_fp16.h>
#include <cstdint>

#define BB 2048
#define NN 64
#define DD 512
#define HH 8
#define LL 3
#define FFD 2048
#define RR 400
#define EE 100000

// ---------------- device scratch ----------------
__device__ __align__(256) __half g_embeH[EE * 512];
__device__ __align__(256) __half g_eW2H[EE * 512];
__device__ __align__(256) __half g_embrH[RR * 512];
__device__ __align__(256) __half g_actH[2 * BB * 512];     // [0]=hH, [1]=embqH
__device__ __align__(256) __half g_ctxH[BB * HH * 512];
__device__ __align__(256) __half g_ffH[BB * 2048];
__device__ __align__(256) __half g_W2h[512 * 512];
__device__ __align__(256) __half g_W1h[512 * 512];
__device__ __align__(256) __half g_Wcomb[LL * 2 * 512 * 512];  // [l][0]=W0, [l][1]=Wq[l]
__device__ __align__(256) __half g_Wkh[LL * 512 * 512];
__device__ __align__(256) __half g_Wvh[LL * 512 * 512];
__device__ __align__(256) __half g_F1h[LL * 2048 * 512];
__device__ __align__(256) __half g_F2h[LL * 512 * 2048];
__device__ __align__(256) float  g_bias2[LL * 1024];           // [l]: 512 zeros | bq[l]
__device__ __align__(256) float  g_rW1[RR * 512];
__device__ __align__(256) float  g_Khat[LL * RR * 512];
__device__ __align__(256) float  g_h[BB * 512];
__device__ __align__(256) float  g_hw0qh[2 * BB * 512];        // [0]=hW0, [1]=qh
__device__ __align__(256) float  g_x[2 * BB * 512];

// ---------------- helpers ----------------
__device__ __forceinline__ uint32_t s2u(const void* p) {
    uint32_t a;
    asm("{ .reg .u64 t; cvta.to.shared.u64 t, %1; cvt.u32.u64 %0, t; }" : "=r"(a) : "l"(p));
    return a;
}
__device__ __forceinline__ void cp16(uint32_t d, const void* s) {
    asm volatile("cp.async.cg.shared.global [%0], [%1], 16;" :: "r"(d), "l"(s));
}
__device__ __forceinline__ void cp_commit() { asm volatile("cp.async.commit_group;" ::: "memory"); }
template<int G> __device__ __forceinline__ void cp_wait() {
    asm volatile("cp.async.wait_group %0;" :: "n"(G) : "memory");
}
__device__ __forceinline__ void ldm4(uint32_t& r0, uint32_t& r1, uint32_t& r2, uint32_t& r3, uint32_t a) {
    asm volatile("ldmatrix.sync.aligned.m8n8.x4.shared.b16 {%0,%1,%2,%3}, [%4];"
        : "=r"(r0), "=r"(r1), "=r"(r2), "=r"(r3) : "r"(a));
}
__device__ __forceinline__ void mma_f16(float* c, const uint32_t* a, const uint32_t* b) {
    asm volatile(
        "mma.sync.aligned.m16n8k16.row.col.f32.f16.f16.f32 "
        "{%0,%1,%2,%3}, {%4,%5,%6,%7}, {%8,%9}, {%0,%1,%2,%3};"
        : "+f"(c[0]), "+f"(c[1]), "+f"(c[2]), "+f"(c[3])
        : "r"(a[0]), "r"(a[1]), "r"(a[2]), "r"(a[3]), "r"(b[0]), "r"(b[1]));
}
// 16B-chunk swizzle within 64B rows: conflict-free ldmatrix
__device__ __forceinline__ int swz4(int row, int c) {
    int s = row & 7;
    return ((c + (s >> 2)) ^ (s & 3)) & 3;
}

// ---------------- fp16 HMMA GEMM, 3-stage cp.async pipeline, 2 CTAs/SM ----------------
// C[m,n] = act( sum_k A[row(m), z*za + k] * B[z*zb + n, k] + bias[z*zbias + n0g + n] )
// kz=1: z is split-K slice (chunks [z*kspan, ...)), C += z*zc, bias z==0 only.
template<int BN, int OUTH>
__global__ void __launch_bounds__(256, 2) gemm_f(
    const __half* __restrict__ A, int a_ld, long long za,
    const int* __restrict__ gidx, int M,
    const __half* __restrict__ B, long long zb, int K,
    const float* __restrict__ bias, long long zbias,
    void* __restrict__ Cv, int ldc, int zn, long long zc,
    int kz, int kspan, int act)
{
    constexpr int WARPS_N = BN / 32;
    constexpr int WARPS_M = 8 / WARPS_N;
    constexpr int WM = 128 / WARPS_M;
    constexpr int MAT_M = WM / 16;
    constexpr int STAGE = (128 + BN) * 64;
    constexpr int UNITS = (128 + BN) * 4;

    extern __shared__ __align__(1024) char smem[];
    int* s_idx = (int*)smem;
    const uint32_t sb = s2u(smem);
    const int tid = threadIdx.x, w = tid >> 5, lane = tid & 31;
    const int wm = w / WARPS_N, wn = w % WARPS_N;
    const int gm0 = blockIdx.y * 128;
    const int bn0 = blockIdx.x * BN;
    const int z = blockIdx.z;
    const int n0g = bn0 + z * zn;

    A += (size_t)z * za;
    B += (size_t)z * zb;
    if (kz && z > 0) bias = nullptr;
    else if (bias) bias += (size_t)z * zbias;

    if (tid < 128) {
        int gr = gm0 + tid;
        if (gr >= M) gr = M - 1;
        s_idx[tid] = gidx ? gidx[gr] : gr;
    }
    __syncthreads();

    const int NCH = K >> 5;
    const int kbeg = kz ? z * kspan : 0;
    const int kcnt = kz ? kspan : NCH;

    auto load_chunk = [&](int c) {
        int s = c % 3;
        int koff = c * 32;
        uint32_t st = sb + 512 + s * STAGE;
#pragma unroll
        for (int it = 0; it < UNITS / 256; it++) {
            int u = tid + it * 256;
            if (u < 512) {
                int r = u >> 2, c16 = u & 3;
                cp16(st + r * 64 + swz4(r, c16) * 16,
                     A + (size_t)s_idx[r] * a_ld + koff + c16 * 8);
            } else {
                int v = u - 512;
                int n = v >> 2, c16 = v & 3;
                cp16(st + 8192 + n * 64 + swz4(n, c16) * 16,
                     B + (size_t)(bn0 + n) * K + koff + c16 * 8);
            }
        }
        cp_commit();
    };

    float acc[MAT_M][4][4];
#pragma unroll
    for (int i = 0; i < MAT_M; i++)
#pragma unroll
        for (int j = 0; j < 4; j++)
#pragma unroll
            for (int q = 0; q < 4; q++) acc[i][j][q] = 0.f;

    load_chunk(kbeg);
    load_chunk(kbeg + 1);

    const int r8 = lane & 7, sel = lane >> 3;

    for (int cc = 0; cc < kcnt; cc++) {
        int c = kbeg + cc;
        cp_wait<1>();
        __syncthreads();
        uint32_t stA = sb + 512 + (c % 3) * STAGE;
        uint32_t stB = stA + 8192;
#pragma unroll
        for (int kt = 0; kt < 2; kt++) {
            uint32_t a[MAT_M][4];
#pragma unroll
            for (int i = 0; i < MAT_M; i++) {
                int ar = wm * WM + i * 16 + r8 + (sel & 1) * 8;
                int ac = kt * 2 + (sel >> 1);
                ldm4(a[i][0], a[i][1], a[i][2], a[i][3],
                     stA + ar * 64 + swz4(ar, ac) * 16);
            }
            uint32_t b[4][2];
#pragma unroll
            for (int p = 0; p < 2; p++) {
                int br = wn * 32 + p * 16 + r8 + (sel >> 1) * 8;
                int bc = kt * 2 + (sel & 1);
                uint32_t t0, t1, t2, t3;
                ldm4(t0, t1, t2, t3, stB + br * 64 + swz4(br, bc) * 16);
                b[2 * p][0] = t0; b[2 * p][1] = t1;
                b[2 * p + 1][0] = t2; b[2 * p + 1][1] = t3;
            }
#pragma unroll
            for (int i = 0; i < MAT_M; i++)
#pragma unroll
                for (int j = 0; j < 4; j++)
                    mma_f16(acc[i][j], a[i], b[j]);
        }
        if (cc + 2 < kcnt) load_chunk(c + 2);
        else cp_commit();
    }

    // epilogue
    const int g = lane >> 2, tig = lane & 3;
#pragma unroll
    for (int i = 0; i < MAT_M; i++) {
#pragma unroll
        for (int half = 0; half < 2; half++) {
            int m = gm0 + wm * WM + i * 16 + g + half * 8;
            if (m < M) {
#pragma unroll
                for (int j = 0; j < 4; j++) {
                    int nc = n0g + wn * 32 + j * 8 + tig * 2;
                    float v0 = acc[i][j][half * 2 + 0];
                    float v1 = acc[i][j][half * 2 + 1];
                    if (bias) { v0 += bias[nc]; v1 += bias[nc + 1]; }
                    if (act)  { v0 = fmaxf(v0, 0.f); v1 = fmaxf(v1, 0.f); }
                    if (OUTH) {
                        __half* Ch = (__half*)Cv + (size_t)z * zc;
                        *(__half2*)&Ch[(size_t)m * ldc + nc] = __floats2half2_rn(v0, v1);
                    } else {
                        float* Cf = (float*)Cv + (size_t)z * zc;
                        float2 o; o.x = v0; o.y = v1;
                        *(float2*)&Cf[(size_t)m * ldc + nc] = o;
                    }
                }
            }
        }
    }
}

// ---------------- conversions ----------------
__global__ void __launch_bounds__(256) convW_h(
    const float* __restrict__ W, int str_k, int str_h, int K, int N,
    __half* __restrict__ B2)
{
    int idx = blockIdx.x * 256 + threadIdx.x;
    if (idx >= K * N) return;
    int n = idx / K, k = idx - n * K;
    float x = W[(size_t)k * str_k + (size_t)(n >> 6) * str_h + (n & 63)];
    B2[(size_t)n * K + k] = __float2half_rn(x);
}

__global__ void __launch_bounds__(128) convA_h(
    const float* __restrict__ src, __half* __restrict__ dst)
{
    size_t i = (size_t)blockIdx.x * 512 + threadIdx.x;
#pragma unroll
    for (int t = 0; t < 4; t++)
        dst[i + t * 128] = __float2half_rn(src[i + t * 128]);
}

__global__ void __launch_bounds__(256) biasfill_k(
    const float* __restrict__ bq, float* __restrict__ bias2)
{
    int l = blockIdx.x;
    for (int t = threadIdx.x; t < 1024; t += 256)
        bias2[l * 1024 + t] = (t < 512) ? 0.f : bq[l * 512 + t - 512];
}

// ---------------- fused attention ----------------
__global__ void __launch_bounds__(256) attn_k(
    const float* __restrict__ qh, const float* __restrict__ Khat,  // [R][512] this layer
    const int* __restrict__ nbr_r, const int* __restrict__ nbr_e,
    const float* __restrict__ masks,
    const float* __restrict__ hW0, const __half* __restrict__ eW2,
    const float* __restrict__ rW1,
    __half* __restrict__ ctxH)
{
    const int b = blockIdx.x;
    const int tid = threadIdx.x;
    const int lane = tid & 31, w = tid >> 5;

    __shared__ float s_q[512];
    __shared__ float s_attn[HH * 64];
    __shared__ int   s_nbr[NN], s_nbe[NN];

    s_q[tid]       = qh[(size_t)b * 512 + tid];
    s_q[tid + 256] = qh[(size_t)b * 512 + tid + 256];
    if (tid < NN) { s_nbr[tid] = nbr_r[b * NN + tid]; s_nbe[tid] = nbr_e[b * NN + tid]; }
    __syncthreads();

    {
        float q0 = s_q[w * 64 + lane], q1 = s_q[w * 64 + lane + 32];
        for (int n = 0; n < NN; n++) {
            int j = s_nbr[n];
            const float* kr = Khat + (size_t)j * 512 + w * 64;
            float p = q0 * kr[lane] + q1 * kr[lane + 32];
#pragma unroll
            for (int o = 16; o; o >>= 1) p += __shfl_xor_sync(0xffffffffu, p, o);
            if (lane == 0)
                s_attn[w * 64 + n] = p * 0.125f - 1e31f * (1.0f - masks[b * NN + n]);
        }
    }
    __syncwarp();
    {
        float s0 = s_attn[w * 64 + lane], s1 = s_attn[w * 64 + lane + 32];
        float m = fmaxf(s0, s1);
#pragma unroll
        for (int o = 16; o; o >>= 1) m = fmaxf(m, __shfl_xor_sync(0xffffffffu, m, o));
        float e0 = expf(s0 - m), e1 = expf(s1 - m);
        float sum = e0 + e1;
#pragma unroll
        for (int o = 16; o; o >>= 1) sum += __shfl_xor_sync(0xffffffffu, sum, o);
        float inv = 1.f / sum;
        s_attn[w * 64 + lane]      = e0 * inv;
        s_attn[w * 64 + lane + 32] = e1 * inv;
    }
    __syncthreads();

    const float hw0a = hW0[(size_t)b * 512 + tid];
    const float hw0b = hW0[(size_t)b * 512 + tid + 256];
    float acc[HH][2];
#pragma unroll
    for (int hh = 0; hh < HH; hh++) { acc[hh][0] = 0.f; acc[hh][1] = 0.f; }

#pragma unroll 2
    for (int n = 0; n < NN; n++) {
        const __half* ep = eW2 + (size_t)s_nbe[n] * 512;
        const float* rp = rW1 + (size_t)s_nbr[n] * 512;
        float v0 = hw0a + __half2float(ep[tid]) + rp[tid];
        float v1 = hw0b + __half2float(ep[tid + 256]) + rp[tid + 256];
        v0 = (v0 > 0.f) ? v0 : 0.01f * v0;
        v1 = (v1 > 0.f) ? v1 : 0.01f * v1;
#pragma unroll
        for (int hh = 0; hh < HH; hh++) {
            float a = s_attn[hh * 64 + n];
            acc[hh][0] += a * v0;
            acc[hh][1] += a * v1;
        }
    }
#pragma unroll
    for (int hh = 0; hh < HH; hh++) {
        __half* cb = ctxH + ((size_t)b * HH + hh) * 512;
        cb[tid]       = __float2half_rn(acc[hh][0]);
        cb[tid + 256] = __float2half_rn(acc[hh][1]);
    }
}

// ---------------- layernorm (+ optional second x, + fp16 out) ----------------
__global__ void __launch_bounds__(128) ln_k(
    float* __restrict__ h, const float* __restrict__ x, const float* __restrict__ x2,
    const float* __restrict__ gamma, const float* __restrict__ beta,
    __half* __restrict__ hH)
{
    const int b = blockIdx.x, tid = threadIdx.x;
    __shared__ float sred[8];
    float4 hv = ((const float4*)(h + (size_t)b * 512))[tid];
    float4 xv = ((const float4*)(x + (size_t)b * 512))[tid];
    float v0 = hv.x + xv.x, v1 = hv.y + xv.y, v2 = hv.z + xv.z, v3 = hv.w + xv.w;
    if (x2) {
        float4 x2v = ((const float4*)(x2 + (size_t)b * 512))[tid];
        v0 += x2v.x; v1 += x2v.y; v2 += x2v.z; v3 += x2v.w;
    }

    float s = v0 + v1 + v2 + v3;
#pragma unroll
    for (int o = 16; o; o >>= 1) s += __shfl_xor_sync(0xffffffffu, s, o);
    if ((tid & 31) == 0) sred[tid >> 5] = s;
    __syncthreads();
    float mean = (sred[0] + sred[1] + sred[2] + sred[3]) * (1.f / 512.f);

    v0 -= mean; v1 -= mean; v2 -= mean; v3 -= mean;
    float sq = v0 * v0 + v1 * v1 + v2 * v2 + v3 * v3;
#pragma unroll
    for (int o = 16; o; o >>= 1) sq += __shfl_xor_sync(0xffffffffu, sq, o);
    if ((tid & 31) == 0) sred[4 + (tid >> 5)] = sq;
    __syncthreads();
    float var = (sred[4] + sred[5] + sred[6] + sred[7]) * (1.f / 512.f);
    float rstd = rsqrtf(var + 1e-5f);

    float4 g = ((const float4*)gamma)[tid];
    float4 be = ((const float4*)beta)[tid];
    float o0 = v0 * rstd * g.x + be.x;
    float o1 = v1 * rstd * g.y + be.y;
    float o2 = v2 * rstd * g.z + be.z;
    float o3 = v3 * rstd * g.w + be.w;
    float4 o; o.x = o0; o.y = o1; o.z = o2; o.w = o3;
    ((float4*)(h + (size_t)b * 512))[tid] = o;

    __half2* d = (__half2*)(hH + (size_t)b * 512 + tid * 4);
    d[0] = __floats2half2_rn(o0, o1);
    d[1] = __floats2half2_rn(o2, o3);
}

// ---------------- init ----------------
__global__ void __launch_bounds__(128) init_k(
    const int* __restrict__ e1, const int* __restrict__ qi,
    const float* __restrict__ emb_e, const float* __restrict__ emb_r,
    float* __restrict__ h, __half* __restrict__ actH,
    float* __restrict__ outq, int writeq)
{
    const int b = blockIdx.x, t = threadIdx.x;
    const float* se = emb_e + (size_t)e1[b] * 512;
    const float* sr = emb_r + (size_t)qi[b] * 512;
    for (int j = t; j < 512; j += 128) {
        float hv = se[j];
        h[(size_t)b * 512 + j] = hv;
        actH[(size_t)b * 512 + j] = __float2half_rn(hv);
        float q = sr[j];
        actH[(size_t)(BB + b) * 512 + j] = __float2half_rn(q);
        if (writeq) outq[(size_t)b * 512 + j] = q;
    }
}

__global__ void copy_k(float* __restrict__ out, const float* __restrict__ in)
{
    int i = blockIdx.x * 256 + threadIdx.x;
    out[i] = in[i];
}

// ---------------- launch ----------------
extern "C" void kernel_launch(void* const* d_in, const int* in_sizes, int n_in,
                              void* d_out, int out_size)
{
    const int*   e1    = (const int*)d_in[0];
    const int*   qidx  = (const int*)d_in[1];
    const int*   nbr_r = (const int*)d_in[2];
    const int*   nbr_e = (const int*)d_in[3];
    const float* masks = (const float*)d_in[4];
    const float* emb_e = (const float*)d_in[5];
    const float* emb_r = (const float*)d_in[6];
    const float* msg_W = (const float*)d_in[7];
    const float* msg_b = (const float*)d_in[8];
    const float* Wq    = (const float*)d_in[9];
    const float* bq    = (const float*)d_in[10];
    const float* Wk    = (const float*)d_in[11];
    const float* bk    = (const float*)d_in[12];
    const float* Wv    = (const float*)d_in[13];
    const float* bv    = (const float*)d_in[14];
    const float* ffW1  = (const float*)d_in[15];
    const float* ffb1  = (const float*)d_in[16];
    const float* ffW2  = (const float*)d_in[17];
    const float* ffb2  = (const float*)d_in[18];
    const float* ln1g  = (const float*)d_in[19];
    const float* ln1b  = (const float*)d_in[20];
    const float* ln2g  = (const float*)d_in[21];
    const float* ln2b  = (const float*)d_in[22];
    float* out = (float*)d_out;

    __half *p_embeH, *p_eW2H, *p_embrH, *p_actH, *p_ctxH, *p_ffH;
    __half *p_W2h, *p_W1h, *p_Wcomb, *p_Wkh, *p_Wvh, *p_F1h, *p_F2h;
    float *p_bias2, *p_rW1, *p_Khat, *p_h, *p_hw0qh, *p_x;
    cudaGetSymbolAddress((void**)&p_embeH, g_embeH);
    cudaGetSymbolAddress((void**)&p_eW2H,  g_eW2H);
    cudaGetSymbolAddress((void**)&p_embrH, g_embrH);
    cudaGetSymbolAddress((void**)&p_actH,  g_actH);
    cudaGetSymbolAddress((void**)&p_ctxH,  g_ctxH);
    cudaGetSymbolAddress((void**)&p_ffH,   g_ffH);
    cudaGetSymbolAddress((void**)&p_W2h,   g_W2h);
    cudaGetSymbolAddress((void**)&p_W1h,   g_W1h);
    cudaGetSymbolAddress((void**)&p_Wcomb, g_Wcomb);
    cudaGetSymbolAddress((void**)&p_Wkh,   g_Wkh);
    cudaGetSymbolAddress((void**)&p_Wvh,   g_Wvh);
    cudaGetSymbolAddress((void**)&p_F1h,   g_F1h);
    cudaGetSymbolAddress((void**)&p_F2h,   g_F2h);
    cudaGetSymbolAddress((void**)&p_bias2, g_bias2);
    cudaGetSymbolAddress((void**)&p_rW1,   g_rW1);
    cudaGetSymbolAddress((void**)&p_Khat,  g_Khat);
    cudaGetSymbolAddress((void**)&p_h,     g_h);
    cudaGetSymbolAddress((void**)&p_hw0qh, g_hw0qh);
    cudaGetSymbolAddress((void**)&p_x,     g_x);

    const int SM3_128 = 512 + 3 * (256 * 64);  // 49664
    const int SM3_64  = 512 + 3 * (192 * 64);  // 37376
    cudaFuncSetAttribute((gemm_f<128, 0>), cudaFuncAttributeMaxDynamicSharedMemorySize, SM3_128);
    cudaFuncSetAttribute((gemm_f<128, 1>), cudaFuncAttributeMaxDynamicSharedMemorySize, SM3_128);
    cudaFuncSetAttribute((gemm_f<64, 0>),  cudaFuncAttributeMaxDynamicSharedMemorySize, SM3_64);

    int writeq = (out_size >= 2 * BB * DD) ? 1 : 0;
    // launches 1-3
    init_k<<<BB, 128>>>(e1, qidx, emb_e, emb_r, p_h, p_actH, out + (size_t)BB * DD, writeq);
    convA_h<<<EE, 128>>>(emb_e, p_embeH);
    convW_h<<<1024, 256>>>(msg_W + 1024 * 512, 512, 64, 512, 512, p_W2h);
    // launch 4: eW2 = emb_e @ W2 + msg_b (profiled slot)
    gemm_f<128, 1><<<dim3(4, (EE + 127) / 128), 256, SM3_128>>>(
        p_embeH, 512, 0, nullptr, EE, p_W2h, 0, 512,
        msg_b, 0, p_eW2H, 512, 0, 0, 0, 0, 0);

    // remaining conversions
    convA_h<<<RR, 128>>>(emb_r, p_embrH);
    convW_h<<<1024, 256>>>(msg_W + 512 * 512, 512, 64, 512, 512, p_W1h);
    biasfill_k<<<LL, 256>>>(bq, p_bias2);
    for (int l = 0; l < LL; l++) {
        convW_h<<<1024, 256>>>(msg_W, 512, 64, 512, 512, p_Wcomb + (size_t)l * 2 * 262144);
        convW_h<<<1024, 256>>>(Wq + (size_t)l * 262144, 64, 32768, 512, 512, p_Wcomb + (size_t)l * 2 * 262144 + 262144);
        convW_h<<<1024, 256>>>(Wk + (size_t)l * 262144, 64, 32768, 512, 512, p_Wkh + (size_t)l * 262144);
        convW_h<<<1024, 256>>>(Wv + (size_t)l * 262144, 64, 32768, 512, 512, p_Wvh + (size_t)l * 262144);
        convW_h<<<4096, 256>>>(ffW1 + (size_t)l * 1048576, 2048, 64, 512, 2048, p_F1h + (size_t)l * 1048576);
        convW_h<<<4096, 256>>>(ffW2 + (size_t)l * 1048576, 512, 64, 2048, 512, p_F2h + (size_t)l * 1048576);
    }

    // rW1 = emb_r @ W1
    gemm_f<128, 0><<<dim3(4, 4), 256, SM3_128>>>(
        p_embrH, 512, 0, nullptr, RR, p_W1h, 0, 512,
        nullptr, 0, p_rW1, 512, 0, 0, 0, 0, 0);
    // Khat[l] = emb_r @ Wk[l] + bk[l], all layers batched over z
    gemm_f<128, 0><<<dim3(4, 4, LL), 256, SM3_128>>>(
        p_embrH, 512, 0, nullptr, RR, p_Wkh, 262144, 512,
        bk, 512, p_Khat, 512, 0, (long long)RR * 512, 0, 0, 0);

    for (int l = 0; l < LL; l++) {
        // z=0: hW0 = h @ W0; z=1: qh = embq @ Wq[l] + bq[l]
        gemm_f<128, 0><<<dim3(4, 16, 2), 256, SM3_128>>>(
            p_actH, 512, (long long)BB * 512, nullptr, BB,
            p_Wcomb + (size_t)l * 2 * 262144, 262144, 512,
            p_bias2 + l * 1024, 512,
            p_hw0qh, 512, 0, (long long)BB * 512, 0, 0, 0);
        attn_k<<<BB, 256>>>(p_hw0qh + (size_t)BB * 512, p_Khat + (size_t)l * RR * 512,
                            nbr_r, nbr_e, masks, p_hw0qh, p_eW2H, p_rW1, p_ctxH);
        // x = ctx @ Wv[l] + bv[l] (z = head)
        gemm_f<64, 0><<<dim3(1, 16, 8), 256, SM3_64>>>(
            p_ctxH, 4096, 512, nullptr, BB,
            p_Wvh + (size_t)l * 262144, 32768, 512,
            bv + l * 512, 0, p_x, 512, 64, 0, 0, 0, 0);
        ln_k<<<BB, 128>>>(p_h, p_x, nullptr, ln1g + l * 512, ln1b + l * 512, p_actH);
        // ffH = fp16(relu(h @ F1 + b1))
        gemm_f<128, 1><<<dim3(16, 16), 256, SM3_128>>>(
            p_actH, 512, 0, nullptr, BB,
            p_F1h + (size_t)l * 1048576, 0, 512,
            ffb1 + l * 2048, 0, p_ffH, 2048, 0, 0, 0, 0, 1);
        // x0/x1 = split-K halves of ff @ F2 (+ b2 on z=0)
        gemm_f<128, 0><<<dim3(4, 16, 2), 256, SM3_128>>>(
            p_ffH, 2048, 0, nullptr, BB,
            p_F2h + (size_t)l * 1048576, 0, 2048,
            ffb2 + l * 512, 0, p_x, 512, 0, (long long)BB * 512, 1, 32, 0);
        ln_k<<<BB, 128>>>(p_h, p_x, p_x + (size_t)BB * 512, ln2g + l * 512, ln2b + l * 512, p_actH);
    }

    copy_k<<<(BB * DD) / 256, 256>>>(out, p_h);
}

// round 10
// speedup vs baseline: 3.9560x; 1.0303x over previous
#include <cuda_runtime.h>
#include <cuda_fp16.h>
#include <cstdint>

#define BB 2048
#define NN 64
#define DD 512
#define HH 8
#define LL 3
#define FFD 2048
#define RR 400
#define EE 100000

// ---------------- device scratch ----------------
__device__ __align__(256) __half g_eW2H[EE * 512];
__device__ __align__(256) __half g_embrH[RR * 512];
__device__ __align__(256) __half g_actH[2 * BB * 512];     // [0]=hH, [1]=embqH
__device__ __align__(256) __half g_ctxH[BB * HH * 512];
__device__ __align__(256) __half g_ffH[BB * 2048];
__device__ __align__(256) __half g_W2h[512 * 512];
__device__ __align__(256) __half g_W1h[512 * 512];
__device__ __align__(256) __half g_Wcomb[LL * 2 * 512 * 512];  // [l][0]=W0, [l][1]=Wq[l]
__device__ __align__(256) __half g_Wkh[LL * 512 * 512];
__device__ __align__(256) __half g_Wvh[LL * 512 * 512];
__device__ __align__(256) __half g_F1h[LL * 2048 * 512];
__device__ __align__(256) __half g_F2h[LL * 512 * 2048];
__device__ __align__(256) float  g_bias2[LL * 1024];           // [l]: 512 zeros | bq[l]
__device__ __align__(256) float  g_rW1[RR * 512];
__device__ __align__(256) float  g_Khat[LL * RR * 512];
__device__ __align__(256) float  g_h[BB * 512];
__device__ __align__(256) float  g_hw0qh[2 * BB * 512];        // [0]=hW0, [1]=qh
__device__ __align__(256) float  g_x[2 * BB * 512];

// ---------------- helpers ----------------
__device__ __forceinline__ uint32_t s2u(const void* p) {
    uint32_t a;
    asm("{ .reg .u64 t; cvta.to.shared.u64 t, %1; cvt.u32.u64 %0, t; }" : "=r"(a) : "l"(p));
    return a;
}
__device__ __forceinline__ void cp16(uint32_t d, const void* s) {
    asm volatile("cp.async.cg.shared.global [%0], [%1], 16;" :: "r"(d), "l"(s));
}
__device__ __forceinline__ void cp_commit() { asm volatile("cp.async.commit_group;" ::: "memory"); }
template<int G> __device__ __forceinline__ void cp_wait() {
    asm volatile("cp.async.wait_group %0;" :: "n"(G) : "memory");
}
__device__ __forceinline__ void ldm4(uint32_t& r0, uint32_t& r1, uint32_t& r2, uint32_t& r3, uint32_t a) {
    asm volatile("ldmatrix.sync.aligned.m8n8.x4.shared.b16 {%0,%1,%2,%3}, [%4];"
        : "=r"(r0), "=r"(r1), "=r"(r2), "=r"(r3) : "r"(a));
}
__device__ __forceinline__ void mma_f16(float* c, const uint32_t* a, const uint32_t* b) {
    asm volatile(
        "mma.sync.aligned.m16n8k16.row.col.f32.f16.f16.f32 "
        "{%0,%1,%2,%3}, {%4,%5,%6,%7}, {%8,%9}, {%0,%1,%2,%3};"
        : "+f"(c[0]), "+f"(c[1]), "+f"(c[2]), "+f"(c[3])
        : "r"(a[0]), "r"(a[1]), "r"(a[2]), "r"(a[3]), "r"(b[0]), "r"(b[1]));
}
// 16B-chunk swizzle within 64B rows: conflict-free ldmatrix
__device__ __forceinline__ int swz4(int row, int c) {
    int s = row & 7;
    return ((c + (s >> 2)) ^ (s & 3)) & 3;
}

// ---------------- fp16 HMMA GEMM, 3-stage cp.async pipeline ----------------
template<int BN, int OUTH>
__global__ void __launch_bounds__(256, 2) gemm_f(
    const __half* __restrict__ A, int a_ld, long long za,
    const int* __restrict__ gidx, int M,
    const __half* __restrict__ B, long long zb, int K,
    const float* __restrict__ bias, long long zbias,
    void* __restrict__ Cv, int ldc, int zn, long long zc,
    int kz, int kspan, int act)
{
    constexpr int WARPS_N = BN / 32;
    constexpr int WARPS_M = 8 / WARPS_N;
    constexpr int WM = 128 / WARPS_M;
    constexpr int MAT_M = WM / 16;
    constexpr int STAGE = (128 + BN) * 64;
    constexpr int UNITS = (128 + BN) * 4;

    extern __shared__ __align__(1024) char smem[];
    int* s_idx = (int*)smem;
    const uint32_t sb = s2u(smem);
    const int tid = threadIdx.x, w = tid >> 5, lane = tid & 31;
    const int wm = w / WARPS_N, wn = w % WARPS_N;
    const int gm0 = blockIdx.y * 128;
    const int bn0 = blockIdx.x * BN;
    const int z = blockIdx.z;
    const int n0g = bn0 + z * zn;

    A += (size_t)z * za;
    B += (size_t)z * zb;
    if (kz && z > 0) bias = nullptr;
    else if (bias) bias += (size_t)z * zbias;

    if (tid < 128) {
        int gr = gm0 + tid;
        if (gr >= M) gr = M - 1;
        s_idx[tid] = gidx ? gidx[gr] : gr;
    }
    __syncthreads();

    const int NCH = K >> 5;
    const int kbeg = kz ? z * kspan : 0;
    const int kcnt = kz ? kspan : NCH;

    auto load_chunk = [&](int c) {
        int s = c % 3;
        int koff = c * 32;
        uint32_t st = sb + 512 + s * STAGE;
#pragma unroll
        for (int it = 0; it < UNITS / 256; it++) {
            int u = tid + it * 256;
            if (u < 512) {
                int r = u >> 2, c16 = u & 3;
                cp16(st + r * 64 + swz4(r, c16) * 16,
                     A + (size_t)s_idx[r] * a_ld + koff + c16 * 8);
            } else {
                int v = u - 512;
                int n = v >> 2, c16 = v & 3;
                cp16(st + 8192 + n * 64 + swz4(n, c16) * 16,
                     B + (size_t)(bn0 + n) * K + koff + c16 * 8);
            }
        }
        cp_commit();
    };

    float acc[MAT_M][4][4];
#pragma unroll
    for (int i = 0; i < MAT_M; i++)
#pragma unroll
        for (int j = 0; j < 4; j++)
#pragma unroll
            for (int q = 0; q < 4; q++) acc[i][j][q] = 0.f;

    load_chunk(kbeg);
    load_chunk(kbeg + 1);

    const int r8 = lane & 7, sel = lane >> 3;

    for (int cc = 0; cc < kcnt; cc++) {
        int c = kbeg + cc;
        cp_wait<1>();
        __syncthreads();
        uint32_t stA = sb + 512 + (c % 3) * STAGE;
        uint32_t stB = stA + 8192;
#pragma unroll
        for (int kt = 0; kt < 2; kt++) {
            uint32_t a[MAT_M][4];
#pragma unroll
            for (int i = 0; i < MAT_M; i++) {
                int ar = wm * WM + i * 16 + r8 + (sel & 1) * 8;
                int ac = kt * 2 + (sel >> 1);
                ldm4(a[i][0], a[i][1], a[i][2], a[i][3],
                     stA + ar * 64 + swz4(ar, ac) * 16);
            }
            uint32_t b[4][2];
#pragma unroll
            for (int p = 0; p < 2; p++) {
                int br = wn * 32 + p * 16 + r8 + (sel >> 1) * 8;
                int bc = kt * 2 + (sel & 1);
                uint32_t t0, t1, t2, t3;
                ldm4(t0, t1, t2, t3, stB + br * 64 + swz4(br, bc) * 16);
                b[2 * p][0] = t0; b[2 * p][1] = t1;
                b[2 * p + 1][0] = t2; b[2 * p + 1][1] = t3;
            }
#pragma unroll
            for (int i = 0; i < MAT_M; i++)
#pragma unroll
                for (int j = 0; j < 4; j++)
                    mma_f16(acc[i][j], a[i], b[j]);
        }
        if (cc + 2 < kcnt) load_chunk(c + 2);
        else cp_commit();
    }

    const int g = lane >> 2, tig = lane & 3;
#pragma unroll
    for (int i = 0; i < MAT_M; i++) {
#pragma unroll
        for (int half = 0; half < 2; half++) {
            int m = gm0 + wm * WM + i * 16 + g + half * 8;
            if (m < M) {
#pragma unroll
                for (int j = 0; j < 4; j++) {
                    int nc = n0g + wn * 32 + j * 8 + tig * 2;
                    float v0 = acc[i][j][half * 2 + 0];
                    float v1 = acc[i][j][half * 2 + 1];
                    if (bias) { v0 += bias[nc]; v1 += bias[nc + 1]; }
                    if (act)  { v0 = fmaxf(v0, 0.f); v1 = fmaxf(v1, 0.f); }
                    if (OUTH) {
                        __half* Ch = (__half*)Cv + (size_t)z * zc;
                        *(__half2*)&Ch[(size_t)m * ldc + nc] = __floats2half2_rn(v0, v1);
                    } else {
                        float* Cf = (float*)Cv + (size_t)z * zc;
                        float2 o; o.x = v0; o.y = v1;
                        *(float2*)&Cf[(size_t)m * ldc + nc] = o;
                    }
                }
            }
        }
    }
}

// ---------------- eW2 GEMM with fused fp32->fp16 A conversion ----------------
// C[m,n] = half( sum_k A_f32[m,k] * B[n,k] + bias[n] ), A: [M][512] fp32, BN=128.
__global__ void __launch_bounds__(256) gemm_cvt(
    const float* __restrict__ A, int M,
    const __half* __restrict__ B, int K,
    const float* __restrict__ bias,
    __half* __restrict__ C, int ldc)
{
    constexpr int STAGE = 256 * 64;   // 16KB: A 8KB + B 8KB
    extern __shared__ __align__(1024) char smem[];
    const uint32_t sb = s2u(smem);
    const int tid = threadIdx.x, w = tid >> 5, lane = tid & 31;
    const int wm = w >> 2, wn = w & 3;     // WARPS_M=2, WARPS_N=4, WM=64
    const int gm0 = blockIdx.y * 128;
    const int bn0 = blockIdx.x * 128;

    const int NCH = K >> 5;

    const int ar_ = tid >> 1;
    const int ah_ = (tid & 1) * 16;
    int agr = gm0 + ar_; if (agr >= M) agr = M - 1;
    const float* Ap = A + (size_t)agr * K + ah_;
    float areg[16];

    auto ldgA = [&](int c) {
        const float* p = Ap + c * 32;
#pragma unroll
        for (int j = 0; j < 4; j++) {
            float4 v = *(const float4*)(p + j * 4);
            areg[j * 4 + 0] = v.x; areg[j * 4 + 1] = v.y;
            areg[j * 4 + 2] = v.z; areg[j * 4 + 3] = v.w;
        }
    };
    auto stsA = [&](int c) {
        uint32_t st = sb + 512 + (c % 3) * STAGE;
#pragma unroll
        for (int q = 0; q < 2; q++) {
            int c16 = (ah_ >> 3) + q;
            uint32_t d = st + ar_ * 64 + swz4(ar_, c16) * 16;
            __half2 h0 = __floats2half2_rn(areg[q * 8 + 0], areg[q * 8 + 1]);
            __half2 h1 = __floats2half2_rn(areg[q * 8 + 2], areg[q * 8 + 3]);
            __half2 h2 = __floats2half2_rn(areg[q * 8 + 4], areg[q * 8 + 5]);
            __half2 h3 = __floats2half2_rn(areg[q * 8 + 6], areg[q * 8 + 7]);
            asm volatile("st.shared.v4.b32 [%0], {%1,%2,%3,%4};"
                :: "r"(d), "r"(*(uint32_t*)&h0), "r"(*(uint32_t*)&h1),
                   "r"(*(uint32_t*)&h2), "r"(*(uint32_t*)&h3));
        }
    };
    auto cpB = [&](int c) {
        uint32_t st = sb + 512 + (c % 3) * STAGE + 8192;
        int koff = c * 32;
#pragma unroll
        for (int it = 0; it < 2; it++) {
            int v = tid + it * 256;
            int n = v >> 2, c16 = v & 3;
            cp16(st + n * 64 + swz4(n, c16) * 16,
                 B + (size_t)(bn0 + n) * K + koff + c16 * 8);
        }
        cp_commit();
    };

    float acc[4][4][4];
#pragma unroll
    for (int i = 0; i < 4; i++)
#pragma unroll
        for (int j = 0; j < 4; j++)
#pragma unroll
            for (int q = 0; q < 4; q++) acc[i][j][q] = 0.f;

    ldgA(0); stsA(0); cpB(0);
    ldgA(1); stsA(1); cpB(1);
    ldgA(2);

    const int r8 = lane & 7, sel = lane >> 3;

    for (int cc = 0; cc < NCH; cc++) {
        cp_wait<1>();
        __syncthreads();
        uint32_t stA = sb + 512 + (cc % 3) * STAGE;
        uint32_t stB = stA + 8192;
#pragma unroll
        for (int kt = 0; kt < 2; kt++) {
            uint32_t a[4][4];
#pragma unroll
            for (int i = 0; i < 4; i++) {
                int ar = wm * 64 + i * 16 + r8 + (sel & 1) * 8;
                int ac = kt * 2 + (sel >> 1);
                ldm4(a[i][0], a[i][1], a[i][2], a[i][3],
                     stA + ar * 64 + swz4(ar, ac) * 16);
            }
            uint32_t b[4][2];
#pragma unroll
            for (int p = 0; p < 2; p++) {
                int br = wn * 32 + p * 16 + r8 + (sel >> 1) * 8;
                int bc = kt * 2 + (sel & 1);
                uint32_t t0, t1, t2, t3;
                ldm4(t0, t1, t2, t3, stB + br * 64 + swz4(br, bc) * 16);
                b[2 * p][0] = t0; b[2 * p][1] = t1;
                b[2 * p + 1][0] = t2; b[2 * p + 1][1] = t3;
            }
#pragma unroll
            for (int i = 0; i < 4; i++)
#pragma unroll
                for (int j = 0; j < 4; j++)
                    mma_f16(acc[i][j], a[i], b[j]);
        }
        if (cc + 2 < NCH) {
            stsA(cc + 2);
            cpB(cc + 2);
            if (cc + 3 < NCH) ldgA(cc + 3);
        } else {
            cp_commit();
        }
    }

    const int g = lane >> 2, tig = lane & 3;
#pragma unroll
    for (int i = 0; i < 4; i++) {
#pragma unroll
        for (int half = 0; half < 2; half++) {
            int m = gm0 + wm * 64 + i * 16 + g + half * 8;
            if (m < M) {
#pragma unroll
                for (int j = 0; j < 4; j++) {
                    int nc = bn0 + wn * 32 + j * 8 + tig * 2;
                    float v0 = acc[i][j][half * 2 + 0] + bias[nc];
                    float v1 = acc[i][j][half * 2 + 1] + bias[nc + 1];
                    *(__half2*)&C[(size_t)m * ldc + nc] = __floats2half2_rn(v0, v1);
                }
            }
        }
    }
}

// ---------------- coalesced transpose weight conversion ----------------
// B2[n*K + k] = half( W[k*str_k + (n>>6)*str_h + (n&63)] )
// grid (K/64, N/64, nm), block 256. W += z*wmat, B2 += z*bmat.
// NOTE: row stride 66 (even) so float2 reads of t[rn][2*ck] stay 8B-aligned.
__global__ void __launch_bounds__(256) convT_k(
    const float* __restrict__ W, int str_k, int str_h, long long wmat,
    int K, __half* __restrict__ B2, long long bmat)
{
    __shared__ float t[64][66];   // [n'][k], even padding for aligned float2 reads
    W += (size_t)blockIdx.z * wmat;
    B2 += (size_t)blockIdx.z * bmat;
    const int k0 = blockIdx.x * 64, n0 = blockIdx.y * 64;
    const float* Wp = W + (size_t)(n0 >> 6) * str_h;
    const int c = threadIdx.x & 63;      // n'
    const int r0 = threadIdx.x >> 6;     // k quad
#pragma unroll
    for (int i = 0; i < 16; i++) {
        int r = r0 + i * 4;
        t[c][r] = Wp[(size_t)(k0 + r) * str_k + c];
    }
    __syncthreads();
    const int ck = threadIdx.x & 31;
    const int rn0 = threadIdx.x >> 5;
#pragma unroll
    for (int i = 0; i < 8; i++) {
        int rn = rn0 + i * 8;
        float2 f = *(const float2*)&t[rn][ck * 2];
        *(__half2*)&B2[(size_t)(n0 + rn) * K + k0 + ck * 2] = __floats2half2_rn(f.x, f.y);
    }
}

__global__ void __launch_bounds__(128) convA_h(
    const float* __restrict__ src, __half* __restrict__ dst)
{
    size_t i = (size_t)blockIdx.x * 512 + threadIdx.x;
#pragma unroll
    for (int t = 0; t < 4; t++)
        dst[i + t * 128] = __float2half_rn(src[i + t * 128]);
}

__global__ void __launch_bounds__(256) biasfill_k(
    const float* __restrict__ bq, float* __restrict__ bias2)
{
    int l = blockIdx.x;
    for (int t = threadIdx.x; t < 1024; t += 256)
        bias2[l * 1024 + t] = (t < 512) ? 0.f : bq[l * 512 + t - 512];
}

// ---------------- fused attention ----------------
__global__ void __launch_bounds__(256) attn_k(
    const float* __restrict__ qh, const float* __restrict__ Khat,
    const int* __restrict__ nbr_r, const int* __restrict__ nbr_e,
    const float* __restrict__ masks,
    const float* __restrict__ hW0, const __half* __restrict__ eW2,
    const float* __restrict__ rW1,
    __half* __restrict__ ctxH)
{
    const int b = blockIdx.x;
    const int tid = threadIdx.x;
    const int lane = tid & 31, w = tid >> 5;

    __shared__ float s_q[512];
    __shared__ float s_attn[HH * 64];
    __shared__ int   s_nbr[NN], s_nbe[NN];

    s_q[tid]       = qh[(size_t)b * 512 + tid];
    s_q[tid + 256] = qh[(size_t)b * 512 + tid + 256];
    if (tid < NN) { s_nbr[tid] = nbr_r[b * NN + tid]; s_nbe[tid] = nbr_e[b * NN + tid]; }
    __syncthreads();

    {
        float q0 = s_q[w * 64 + lane], q1 = s_q[w * 64 + lane + 32];
        for (int n = 0; n < NN; n++) {
            int j = s_nbr[n];
            const float* kr = Khat + (size_t)j * 512 + w * 64;
            float p = q0 * kr[lane] + q1 * kr[lane + 32];
#pragma unroll
            for (int o = 16; o; o >>= 1) p += __shfl_xor_sync(0xffffffffu, p, o);
            if (lane == 0)
                s_attn[w * 64 + n] = p * 0.125f - 1e31f * (1.0f - masks[b * NN + n]);
        }
    }
    __syncwarp();
    {
        float s0 = s_attn[w * 64 + lane], s1 = s_attn[w * 64 + lane + 32];
        float m = fmaxf(s0, s1);
#pragma unroll
        for (int o = 16; o; o >>= 1) m = fmaxf(m, __shfl_xor_sync(0xffffffffu, m, o));
        float e0 = expf(s0 - m), e1 = expf(s1 - m);
        float sum = e0 + e1;
#pragma unroll
        for (int o = 16; o; o >>= 1) sum += __shfl_xor_sync(0xffffffffu, sum, o);
        float inv = 1.f / sum;
        s_attn[w * 64 + lane]      = e0 * inv;
        s_attn[w * 64 + lane + 32] = e1 * inv;
    }
    __syncthreads();

    const float hw0a = hW0[(size_t)b * 512 + tid];
    const float hw0b = hW0[(size_t)b * 512 + tid + 256];
    float acc[HH][2];
#pragma unroll
    for (int hh = 0; hh < HH; hh++) { acc[hh][0] = 0.f; acc[hh][1] = 0.f; }

#pragma unroll 2
    for (int n = 0; n < NN; n++) {
        const __half* ep = eW2 + (size_t)s_nbe[n] * 512;
        const float* rp = rW1 + (size_t)s_nbr[n] * 512;
        float v0 = hw0a + __half2float(ep[tid]) + rp[tid];
        float v1 = hw0b + __half2float(ep[tid + 256]) + rp[tid + 256];
        v0 = (v0 > 0.f) ? v0 : 0.01f * v0;
        v1 = (v1 > 0.f) ? v1 : 0.01f * v1;
#pragma unroll
        for (int hh = 0; hh < HH; hh++) {
            float a = s_attn[hh * 64 + n];
            acc[hh][0] += a * v0;
            acc[hh][1] += a * v1;
        }
    }
#pragma unroll
    for (int hh = 0; hh < HH; hh++) {
        __half* cb = ctxH + ((size_t)b * HH + hh) * 512;
        cb[tid]       = __float2half_rn(acc[hh][0]);
        cb[tid + 256] = __float2half_rn(acc[hh][1]);
    }
}

// ---------------- layernorm ----------------
__global__ void __launch_bounds__(128) ln_k(
    float* __restrict__ h, const float* __restrict__ x, const float* __restrict__ x2,
    const float* __restrict__ gamma, const float* __restrict__ beta,
    __half* __restrict__ hH)
{
    const int b = blockIdx.x, tid = threadIdx.x;
    __shared__ float sred[8];
    float4 hv = ((const float4*)(h + (size_t)b * 512))[tid];
    float4 xv = ((const float4*)(x + (size_t)b * 512))[tid];
    float v0 = hv.x + xv.x, v1 = hv.y + xv.y, v2 = hv.z + xv.z, v3 = hv.w + xv.w;
    if (x2) {
        float4 x2v = ((const float4*)(x2 + (size_t)b * 512))[tid];
        v0 += x2v.x; v1 += x2v.y; v2 += x2v.z; v3 += x2v.w;
    }

    float s = v0 + v1 + v2 + v3;
#pragma unroll
    for (int o = 16; o; o >>= 1) s += __shfl_xor_sync(0xffffffffu, s, o);
    if ((tid & 31) == 0) sred[tid >> 5] = s;
    __syncthreads();
    float mean = (sred[0] + sred[1] + sred[2] + sred[3]) * (1.f / 512.f);

    v0 -= mean; v1 -= mean; v2 -= mean; v3 -= mean;
    float sq = v0 * v0 + v1 * v1 + v2 * v2 + v3 * v3;
#pragma unroll
    for (int o = 16; o; o >>= 1) sq += __shfl_xor_sync(0xffffffffu, sq, o);
    if ((tid & 31) == 0) sred[4 + (tid >> 5)] = sq;
    __syncthreads();
    float var = (sred[4] + sred[5] + sred[6] + sred[7]) * (1.f / 512.f);
    float rstd = rsqrtf(var + 1e-5f);

    float4 g = ((const float4*)gamma)[tid];
    float4 be = ((const float4*)beta)[tid];
    float o0 = v0 * rstd * g.x + be.x;
    float o1 = v1 * rstd * g.y + be.y;
    float o2 = v2 * rstd * g.z + be.z;
    float o3 = v3 * rstd * g.w + be.w;
    float4 o; o.x = o0; o.y = o1; o.z = o2; o.w = o3;
    ((float4*)(h + (size_t)b * 512))[tid] = o;

    __half2* d = (__half2*)(hH + (size_t)b * 512 + tid * 4);
    d[0] = __floats2half2_rn(o0, o1);
    d[1] = __floats2half2_rn(o2, o3);
}

// ---------------- init ----------------
__global__ void __launch_bounds__(128) init_k(
    const int* __restrict__ e1, const int* __restrict__ qi,
    const float* __restrict__ emb_e, const float* __restrict__ emb_r,
    float* __restrict__ h, __half* __restrict__ actH,
    float* __restrict__ outq, int writeq)
{
    const int b = blockIdx.x, t = threadIdx.x;
    const float* se = emb_e + (size_t)e1[b] * 512;
    const float* sr = emb_r + (size_t)qi[b] * 512;
    for (int j = t; j < 512; j += 128) {
        float hv = se[j];
        h[(size_t)b * 512 + j] = hv;
        actH[(size_t)b * 512 + j] = __float2half_rn(hv);
        float q = sr[j];
        actH[(size_t)(BB + b) * 512 + j] = __float2half_rn(q);
        if (writeq) outq[(size_t)b * 512 + j] = q;
    }
}

__global__ void copy_k(float* __restrict__ out, const float* __restrict__ in)
{
    int i = blockIdx.x * 256 + threadIdx.x;
    out[i] = in[i];
}

// ---------------- launch ----------------
extern "C" void kernel_launch(void* const* d_in, const int* in_sizes, int n_in,
                              void* d_out, int out_size)
{
    const int*   e1    = (const int*)d_in[0];
    const int*   qidx  = (const int*)d_in[1];
    const int*   nbr_r = (const int*)d_in[2];
    const int*   nbr_e = (const int*)d_in[3];
    const float* masks = (const float*)d_in[4];
    const float* emb_e = (const float*)d_in[5];
    const float* emb_r = (const float*)d_in[6];
    const float* msg_W = (const float*)d_in[7];
    const float* msg_b = (const float*)d_in[8];
    const float* Wq    = (const float*)d_in[9];
    const float* bq    = (const float*)d_in[10];
    const float* Wk    = (const float*)d_in[11];
    const float* bk    = (const float*)d_in[12];
    const float* Wv    = (const float*)d_in[13];
    const float* bv    = (const float*)d_in[14];
    const float* ffW1  = (const float*)d_in[15];
    const float* ffb1  = (const float*)d_in[16];
    const float* ffW2  = (const float*)d_in[17];
    const float* ffb2  = (const float*)d_in[18];
    const float* ln1g  = (const float*)d_in[19];
    const float* ln1b  = (const float*)d_in[20];
    const float* ln2g  = (const float*)d_in[21];
    const float* ln2b  = (const float*)d_in[22];
    float* out = (float*)d_out;

    __half *p_eW2H, *p_embrH, *p_actH, *p_ctxH, *p_ffH;
    __half *p_W2h, *p_W1h, *p_Wcomb, *p_Wkh, *p_Wvh, *p_F1h, *p_F2h;
    float *p_bias2, *p_rW1, *p_Khat, *p_h, *p_hw0qh, *p_x;
    cudaGetSymbolAddress((void**)&p_eW2H,  g_eW2H);
    cudaGetSymbolAddress((void**)&p_embrH, g_embrH);
    cudaGetSymbolAddress((void**)&p_actH,  g_actH);
    cudaGetSymbolAddress((void**)&p_ctxH,  g_ctxH);
    cudaGetSymbolAddress((void**)&p_ffH,   g_ffH);
    cudaGetSymbolAddress((void**)&p_W2h,   g_W2h);
    cudaGetSymbolAddress((void**)&p_W1h,   g_W1h);
    cudaGetSymbolAddress((void**)&p_Wcomb, g_Wcomb);
    cudaGetSymbolAddress((void**)&p_Wkh,   g_Wkh);
    cudaGetSymbolAddress((void**)&p_Wvh,   g_Wvh);
    cudaGetSymbolAddress((void**)&p_F1h,   g_F1h);
    cudaGetSymbolAddress((void**)&p_F2h,   g_F2h);
    cudaGetSymbolAddress((void**)&p_bias2, g_bias2);
    cudaGetSymbolAddress((void**)&p_rW1,   g_rW1);
    cudaGetSymbolAddress((void**)&p_Khat,  g_Khat);
    cudaGetSymbolAddress((void**)&p_h,     g_h);
    cudaGetSymbolAddress((void**)&p_hw0qh, g_hw0qh);
    cudaGetSymbolAddress((void**)&p_x,     g_x);

    const int SM3_128 = 512 + 3 * (256 * 64);  // 49664
    const int SM3_64  = 512 + 3 * (192 * 64);  // 37376
    cudaFuncSetAttribute((gemm_f<128, 0>), cudaFuncAttributeMaxDynamicSharedMemorySize, SM3_128);
    cudaFuncSetAttribute((gemm_f<128, 1>), cudaFuncAttributeMaxDynamicSharedMemorySize, SM3_128);
    cudaFuncSetAttribute((gemm_f<64, 0>),  cudaFuncAttributeMaxDynamicSharedMemorySize, SM3_128);
    cudaFuncSetAttribute(gemm_cvt,         cudaFuncAttributeMaxDynamicSharedMemorySize, SM3_128);

    int writeq = (out_size >= 2 * BB * DD) ? 1 : 0;
    init_k<<<BB, 128>>>(e1, qidx, emb_e, emb_r, p_h, p_actH, out + (size_t)BB * DD, writeq);
    // W2, W1 conversions (coalesced transpose)
    convT_k<<<dim3(8, 8, 1), 256>>>(msg_W + 1024 * 512, 512, 64, 0, 512, p_W2h, 0);
    convT_k<<<dim3(8, 8, 1), 256>>>(msg_W + 512 * 512, 512, 64, 0, 512, p_W1h, 0);
    // eW2 = emb_e @ W2 + msg_b, fused fp32->fp16 A conversion
    gemm_cvt<<<dim3(4, (EE + 127) / 128), 256, SM3_128>>>(
        emb_e, EE, p_W2h, 512, msg_b, p_eW2H, 512);

    convA_h<<<RR, 128>>>(emb_r, p_embrH);
    biasfill_k<<<LL, 256>>>(bq, p_bias2);
    // W0 replicated into Wcomb[l][0] (wmat=0 reads same source), Wq into Wcomb[l][1]
    convT_k<<<dim3(8, 8, LL), 256>>>(msg_W, 512, 64, 0, 512, p_Wcomb, 524288);
    convT_k<<<dim3(8, 8, LL), 256>>>(Wq, 64, 32768, 262144, 512, p_Wcomb + 262144, 524288);
    convT_k<<<dim3(8, 8, LL), 256>>>(Wk, 64, 32768, 262144, 512, p_Wkh, 262144);
    convT_k<<<dim3(8, 8, LL), 256>>>(Wv, 64, 32768, 262144, 512, p_Wvh, 262144);
    convT_k<<<dim3(8, 32, LL), 256>>>(ffW1, 2048, 64, 1048576, 512, p_F1h, 1048576);
    convT_k<<<dim3(32, 8, LL), 256>>>(ffW2, 512, 64, 1048576, 2048, p_F2h, 1048576);

    // rW1 = emb_r @ W1
    gemm_f<128, 0><<<dim3(4, 4), 256, SM3_128>>>(
        p_embrH, 512, 0, nullptr, RR, p_W1h, 0, 512,
        nullptr, 0, p_rW1, 512, 0, 0, 0, 0, 0);
    // Khat[l] = emb_r @ Wk[l] + bk[l]
    gemm_f<128, 0><<<dim3(4, 4, LL), 256, SM3_128>>>(
        p_embrH, 512, 0, nullptr, RR, p_Wkh, 262144, 512,
        bk, 512, p_Khat, 512, 0, (long long)RR * 512, 0, 0, 0);

    for (int l = 0; l < LL; l++) {
        // z=0: hW0 = h @ W0; z=1: qh = embq @ Wq[l] + bq[l]
        gemm_f<128, 0><<<dim3(4, 16, 2), 256, SM3_128>>>(
            p_actH, 512, (long long)BB * 512, nullptr, BB,
            p_Wcomb + (size_t)l * 2 * 262144, 262144, 512,
            p_bias2 + l * 1024, 512,
            p_hw0qh, 512, 0, (long long)BB * 512, 0, 0, 0);
        attn_k<<<BB, 256>>>(p_hw0qh + (size_t)BB * 512, p_Khat + (size_t)l * RR * 512,
                            nbr_r, nbr_e, masks, p_hw0qh, p_eW2H, p_rW1, p_ctxH);
        // x = ctx @ Wv[l] + bv[l] (z = head)
        gemm_f<64, 0><<<dim3(1, 16, 8), 256, SM3_64>>>(
            p_ctxH, 4096, 512, nullptr, BB,
            p_Wvh + (size_t)l * 262144, 32768, 512,
            bv + l * 512, 0, p_x, 512, 64, 0, 0, 0, 0);
        ln_k<<<BB, 128>>>(p_h, p_x, nullptr, ln1g + l * 512, ln1b + l * 512, p_actH);
        // ffH = fp16(relu(h @ F1 + b1))
        gemm_f<128, 1><<<dim3(16, 16), 256, SM3_128>>>(
            p_actH, 512, 0, nullptr, BB,
            p_F1h + (size_t)l * 1048576, 0, 512,
            ffb1 + l * 2048, 0, p_ffH, 2048, 0, 0, 0, 0, 1);
        // x0/x1 = split-K halves of ff @ F2 (+ b2 on z=0)
        gemm_f<128, 0><<<dim3(4, 16, 2), 256, SM3_128>>>(
            p_ffH, 2048, 0, nullptr, BB,
            p_F2h + (size_t)l * 1048576, 0, 2048,
            ffb2 + l * 512, 0, p_x, 512, 0, (long long)BB * 512, 1, 32, 0);
        ln_k<<<BB, 128>>>(p_h, p_x, p_x + (size_t)BB * 512, ln2g + l * 512, ln2b + l * 512, p_actH);
    }

    copy_k<<<(BB * DD) / 256, 256>>>(out, p_h);
}

// round 11
// speedup vs baseline: 4.3666x; 1.1038x over previous
#include <cuda_runtime.h>
#include <cuda_fp16.h>
#include <cstdint>

#define BB 2048
#define NN 64
#define DD 512
#define HH 8
#define LL 3
#define FFD 2048
#define RR 400
#define EE 100000

// ---------------- device scratch ----------------
__device__ __align__(256) __half g_embeH[EE * 512];
__device__ __align__(256) __half g_eW2H[EE * 512];
__device__ __align__(256) __half g_embrH[RR * 512];
__device__ __align__(256) __half g_actH[2 * BB * 512];     // [0]=hH, [1]=embqH
__device__ __align__(256) __half g_ctxH[BB * HH * 512];
__device__ __align__(256) __half g_ffH[BB * 2048];
__device__ __align__(256) __half g_rW1H[RR * 512];
__device__ __align__(256) __half g_W2h[512 * 512];
__device__ __align__(256) __half g_W1h[512 * 512];
__device__ __align__(256) __half g_Wcomb[LL * 2 * 512 * 512];  // [l][0]=W0, [l][1]=Wq[l]
__device__ __align__(256) __half g_Wkh[LL * 512 * 512];
__device__ __align__(256) __half g_Wvh[LL * 512 * 512];
__device__ __align__(256) __half g_F1h[LL * 2048 * 512];
__device__ __align__(256) __half g_F2h[LL * 512 * 2048];
__device__ __align__(256) float  g_bias2[LL * 1024];           // [l]: 512 zeros | bq[l]
__device__ __align__(256) float  g_Khat[LL * RR * 512];
__device__ __align__(256) float  g_h[BB * 512];
__device__ __align__(256) float  g_hw0qh[2 * BB * 512];        // [0]=hW0, [1]=qh
__device__ __align__(256) float  g_x[2 * BB * 512];

// ---------------- helpers ----------------
__device__ __forceinline__ uint32_t s2u(const void* p) {
    uint32_t a;
    asm("{ .reg .u64 t; cvta.to.shared.u64 t, %1; cvt.u32.u64 %0, t; }" : "=r"(a) : "l"(p));
    return a;
}
__device__ __forceinline__ void cp16(uint32_t d, const void* s) {
    asm volatile("cp.async.cg.shared.global [%0], [%1], 16;" :: "r"(d), "l"(s));
}
__device__ __forceinline__ void cp_commit() { asm volatile("cp.async.commit_group;" ::: "memory"); }
template<int G> __device__ __forceinline__ void cp_wait() {
    asm volatile("cp.async.wait_group %0;" :: "n"(G) : "memory");
}
__device__ __forceinline__ void ldm4(uint32_t& r0, uint32_t& r1, uint32_t& r2, uint32_t& r3, uint32_t a) {
    asm volatile("ldmatrix.sync.aligned.m8n8.x4.shared.b16 {%0,%1,%2,%3}, [%4];"
        : "=r"(r0), "=r"(r1), "=r"(r2), "=r"(r3) : "r"(a));
}
__device__ __forceinline__ void mma_f16(float* c, const uint32_t* a, const uint32_t* b) {
    asm volatile(
        "mma.sync.aligned.m16n8k16.row.col.f32.f16.f16.f32 "
        "{%0,%1,%2,%3}, {%4,%5,%6,%7}, {%8,%9}, {%0,%1,%2,%3};"
        : "+f"(c[0]), "+f"(c[1]), "+f"(c[2]), "+f"(c[3])
        : "r"(a[0]), "r"(a[1]), "r"(a[2]), "r"(a[3]), "r"(b[0]), "r"(b[1]));
}
// SW128: 16B chunk swizzle within 128B rows
__device__ __forceinline__ uint32_t ofs128(int row, int c) {
    return (uint32_t)(row * 128 + ((c ^ (row & 7)) << 4));
}

// ---------------- fp16 HMMA GEMM, BK=64, 3-stage cp.async pipeline ----------------
// C[m,n] = act( sum_k A[row(m), z*za + k] * B[z*zb + n, k] + bias[z*zbias + n0g + n] )
// kz=1: z is split-K slice (chunks [z*kspan, ...)), C += z*zc, bias z==0 only.
template<int BN, int OUTH>
__global__ void __launch_bounds__(256, 2) gemm_f2(
    const __half* __restrict__ A, int a_ld, long long za,
    const int* __restrict__ gidx, int M,
    const __half* __restrict__ B, long long zb, int K,
    const float* __restrict__ bias, long long zbias,
    void* __restrict__ Cv, int ldc, int zn, long long zc,
    int kz, int kspan, int act)
{
    constexpr int WARPS_N = BN / 32;
    constexpr int WARPS_M = 8 / WARPS_N;
    constexpr int WM = 128 / WARPS_M;
    constexpr int MAT_M = WM / 16;
    constexpr int STAGE = (128 + BN) * 128;      // bytes per stage (BK=64 halves)
    constexpr int UNITS = (128 + BN) * 8;        // 16B chunks per stage

    extern __shared__ __align__(1024) char smem[];
    int* s_idx = (int*)smem;
    const uint32_t sb = s2u(smem);
    const int tid = threadIdx.x, w = tid >> 5, lane = tid & 31;
    const int wm = w / WARPS_N, wn = w % WARPS_N;
    const int gm0 = blockIdx.y * 128;
    const int bn0 = blockIdx.x * BN;
    const int z = blockIdx.z;
    const int n0g = bn0 + z * zn;

    A += (size_t)z * za;
    B += (size_t)z * zb;
    if (kz && z > 0) bias = nullptr;
    else if (bias) bias += (size_t)z * zbias;

    if (tid < 128) {
        int gr = gm0 + tid;
        if (gr >= M) gr = M - 1;
        s_idx[tid] = gidx ? gidx[gr] : gr;
    }
    __syncthreads();

    const int NCH = K >> 6;
    const int kbeg = kz ? z * kspan : 0;
    const int kcnt = kz ? kspan : NCH;

    auto load_chunk = [&](int c) {
        int s = c % 3;
        int koff = c * 64;
        uint32_t st = sb + 512 + s * STAGE;
#pragma unroll
        for (int it = 0; it < UNITS / 256; it++) {
            int u = tid + it * 256;
            if (u < 1024) {
                int r = u >> 3, c16 = u & 7;
                cp16(st + ofs128(r, c16),
                     A + (size_t)s_idx[r] * a_ld + koff + c16 * 8);
            } else {
                int v = u - 1024;
                int n = v >> 3, c16 = v & 7;
                cp16(st + 16384 + ofs128(n, c16),
                     B + (size_t)(bn0 + n) * K + koff + c16 * 8);
            }
        }
        cp_commit();
    };

    float acc[MAT_M][4][4];
#pragma unroll
    for (int i = 0; i < MAT_M; i++)
#pragma unroll
        for (int j = 0; j < 4; j++)
#pragma unroll
            for (int q = 0; q < 4; q++) acc[i][j][q] = 0.f;

    load_chunk(kbeg);
    load_chunk(kbeg + 1);

    const int r8 = lane & 7, sel = lane >> 3;

    for (int cc = 0; cc < kcnt; cc++) {
        int c = kbeg + cc;
        cp_wait<1>();
        __syncthreads();
        uint32_t stA = sb + 512 + (c % 3) * STAGE;
        uint32_t stB = stA + 16384;
#pragma unroll
        for (int kt = 0; kt < 4; kt++) {
            uint32_t a[MAT_M][4];
#pragma unroll
            for (int i = 0; i < MAT_M; i++) {
                int ar = wm * WM + i * 16 + r8 + (sel & 1) * 8;
                int ac = kt * 2 + (sel >> 1);
                ldm4(a[i][0], a[i][1], a[i][2], a[i][3], stA + ofs128(ar, ac));
            }
            uint32_t b[4][2];
#pragma unroll
            for (int p = 0; p < 2; p++) {
                int br = wn * 32 + p * 16 + r8 + (sel >> 1) * 8;
                int bc = kt * 2 + (sel & 1);
                uint32_t t0, t1, t2, t3;
                ldm4(t0, t1, t2, t3, stB + ofs128(br, bc));
                b[2 * p][0] = t0; b[2 * p][1] = t1;
                b[2 * p + 1][0] = t2; b[2 * p + 1][1] = t3;
            }
#pragma unroll
            for (int i = 0; i < MAT_M; i++)
#pragma unroll
                for (int j = 0; j < 4; j++)
                    mma_f16(acc[i][j], a[i], b[j]);
        }
        if (cc + 2 < kcnt) load_chunk(c + 2);
        else cp_commit();
    }

    const int g = lane >> 2, tig = lane & 3;
#pragma unroll
    for (int i = 0; i < MAT_M; i++) {
#pragma unroll
        for (int half = 0; half < 2; half++) {
            int m = gm0 + wm * WM + i * 16 + g + half * 8;
            if (m < M) {
#pragma unroll
                for (int j = 0; j < 4; j++) {
                    int nc = n0g + wn * 32 + j * 8 + tig * 2;
                    float v0 = acc[i][j][half * 2 + 0];
                    float v1 = acc[i][j][half * 2 + 1];
                    if (bias) { v0 += bias[nc]; v1 += bias[nc + 1]; }
                    if (act)  { v0 = fmaxf(v0, 0.f); v1 = fmaxf(v1, 0.f); }
                    if (OUTH) {
                        __half* Ch = (__half*)Cv + (size_t)z * zc;
                        *(__half2*)&Ch[(size_t)m * ldc + nc] = __floats2half2_rn(v0, v1);
                    } else {
                        float* Cf = (float*)Cv + (size_t)z * zc;
                        float2 o; o.x = v0; o.y = v1;
                        *(float2*)&Cf[(size_t)m * ldc + nc] = o;
                    }
                }
            }
        }
    }
}

// ---------------- coalesced transpose weight conversion ----------------
// B2[n*K + k] = half( W[k*str_k + (n>>6)*str_h + (n&63)] ); stride 66 keeps float2 aligned
__global__ void __launch_bounds__(256) convT_k(
    const float* __restrict__ W, int str_k, int str_h, long long wmat,
    int K, __half* __restrict__ B2, long long bmat)
{
    __shared__ float t[64][66];
    W += (size_t)blockIdx.z * wmat;
    B2 += (size_t)blockIdx.z * bmat;
    const int k0 = blockIdx.x * 64, n0 = blockIdx.y * 64;
    const float* Wp = W + (size_t)(n0 >> 6) * str_h;
    const int c = threadIdx.x & 63;
    const int r0 = threadIdx.x >> 6;
#pragma unroll
    for (int i = 0; i < 16; i++) {
        int r = r0 + i * 4;
        t[c][r] = Wp[(size_t)(k0 + r) * str_k + c];
    }
    __syncthreads();
    const int ck = threadIdx.x & 31;
    const int rn0 = threadIdx.x >> 5;
#pragma unroll
    for (int i = 0; i < 8; i++) {
        int rn = rn0 + i * 8;
        float2 f = *(const float2*)&t[rn][ck * 2];
        *(__half2*)&B2[(size_t)(n0 + rn) * K + k0 + ck * 2] = __floats2half2_rn(f.x, f.y);
    }
}

__global__ void __launch_bounds__(128) convA_h(
    const float* __restrict__ src, __half* __restrict__ dst)
{
    size_t i = (size_t)blockIdx.x * 512 + threadIdx.x;
#pragma unroll
    for (int t = 0; t < 4; t++)
        dst[i + t * 128] = __float2half_rn(src[i + t * 128]);
}

__global__ void __launch_bounds__(256) biasfill_k(
    const float* __restrict__ bq, float* __restrict__ bias2)
{
    int l = blockIdx.x;
    for (int t = threadIdx.x; t < 1024; t += 256)
        bias2[l * 1024 + t] = (t < 512) ? 0.f : bq[l * 512 + t - 512];
}

// ---------------- fused attention (masked-neighbor skip, fp16 tables) ----------------
__global__ void __launch_bounds__(256) attn_k(
    const float* __restrict__ qh, const float* __restrict__ Khat,
    const int* __restrict__ nbr_r, const int* __restrict__ nbr_e,
    const float* __restrict__ masks,
    const float* __restrict__ hW0, const __half* __restrict__ eW2,
    const __half* __restrict__ rW1H,
    __half* __restrict__ ctxH)
{
    const int b = blockIdx.x;
    const int tid = threadIdx.x;
    const int lane = tid & 31, w = tid >> 5;

    __shared__ float s_q[512];
    __shared__ float s_attn[HH * 64];
    __shared__ int   s_nbr[NN], s_nbe[NN], s_act[NN];
    __shared__ int   s_wc[2];
    __shared__ unsigned s_keepbits[2];

    s_q[tid]       = qh[(size_t)b * 512 + tid];
    s_q[tid + 256] = qh[(size_t)b * 512 + tid + 256];
    if (tid < NN) { s_nbr[tid] = nbr_r[b * NN + tid]; s_nbe[tid] = nbr_e[b * NN + tid]; }
    if (w < 2) {
        bool keep = masks[b * NN + tid] > 0.5f;
        unsigned bal = __ballot_sync(0xffffffffu, keep);
        if (lane == 0) { s_wc[w] = __popc(bal); s_keepbits[w] = bal; }
    }
    __syncthreads();
    // compact active list
    if (w < 2) {
        unsigned bal = s_keepbits[w];
        bool keep = (bal >> lane) & 1u;
        int rank = __popc(bal & ((1u << lane) - 1u)) + (w ? s_wc[0] : 0);
        if (keep) s_act[rank] = tid;
    }
    const int nact = s_wc[0] + s_wc[1];
    __syncthreads();

    // scores (skip masked: their softmax weight is exactly 0)
    {
        unsigned kb0 = s_keepbits[0], kb1 = s_keepbits[1];
        float q0 = s_q[w * 64 + lane], q1 = s_q[w * 64 + lane + 32];
        for (int n = 0; n < NN; n++) {
            bool keep = (n < 32) ? ((kb0 >> n) & 1u) : ((kb1 >> (n - 32)) & 1u);
            if (!keep) {
                if (lane == 0) s_attn[w * 64 + n] = -1e31f;
                continue;
            }
            int j = s_nbr[n];
            const float* kr = Khat + (size_t)j * 512 + w * 64;
            float p = q0 * kr[lane] + q1 * kr[lane + 32];
#pragma unroll
            for (int o = 16; o; o >>= 1) p += __shfl_xor_sync(0xffffffffu, p, o);
            if (lane == 0) s_attn[w * 64 + n] = p * 0.125f;
        }
    }
    __syncwarp();
    {
        float s0 = s_attn[w * 64 + lane], s1 = s_attn[w * 64 + lane + 32];
        float m = fmaxf(s0, s1);
#pragma unroll
        for (int o = 16; o; o >>= 1) m = fmaxf(m, __shfl_xor_sync(0xffffffffu, m, o));
        float e0 = expf(s0 - m), e1 = expf(s1 - m);
        float sum = e0 + e1;
#pragma unroll
        for (int o = 16; o; o >>= 1) sum += __shfl_xor_sync(0xffffffffu, sum, o);
        float inv = 1.f / sum;
        s_attn[w * 64 + lane]      = e0 * inv;
        s_attn[w * 64 + lane + 32] = e1 * inv;
    }
    __syncthreads();

    const float hw0a = hW0[(size_t)b * 512 + tid];
    const float hw0b = hW0[(size_t)b * 512 + tid + 256];
    float acc[HH][2];
#pragma unroll
    for (int hh = 0; hh < HH; hh++) { acc[hh][0] = 0.f; acc[hh][1] = 0.f; }

    for (int ii = 0; ii < nact; ii++) {
        int n = s_act[ii];
        const __half* ep = eW2 + (size_t)s_nbe[n] * 512;
        const __half* rp = rW1H + (size_t)s_nbr[n] * 512;
        float v0 = hw0a + __half2float(ep[tid]) + __half2float(rp[tid]);
        float v1 = hw0b + __half2float(ep[tid + 256]) + __half2float(rp[tid + 256]);
        v0 = (v0 > 0.f) ? v0 : 0.01f * v0;
        v1 = (v1 > 0.f) ? v1 : 0.01f * v1;
#pragma unroll
        for (int hh = 0; hh < HH; hh++) {
            float a = s_attn[hh * 64 + n];
            acc[hh][0] += a * v0;
            acc[hh][1] += a * v1;
        }
    }
#pragma unroll
    for (int hh = 0; hh < HH; hh++) {
        __half* cb = ctxH + ((size_t)b * HH + hh) * 512;
        cb[tid]       = __float2half_rn(acc[hh][0]);
        cb[tid + 256] = __float2half_rn(acc[hh][1]);
    }
}

// ---------------- layernorm ----------------
__global__ void __launch_bounds__(128) ln_k(
    float* __restrict__ h, const float* __restrict__ x, const float* __restrict__ x2,
    const float* __restrict__ gamma, const float* __restrict__ beta,
    __half* __restrict__ hH)
{
    const int b = blockIdx.x, tid = threadIdx.x;
    __shared__ float sred[8];
    float4 hv = ((const float4*)(h + (size_t)b * 512))[tid];
    float4 xv = ((const float4*)(x + (size_t)b * 512))[tid];
    float v0 = hv.x + xv.x, v1 = hv.y + xv.y, v2 = hv.z + xv.z, v3 = hv.w + xv.w;
    if (x2) {
        float4 x2v = ((const float4*)(x2 + (size_t)b * 512))[tid];
        v0 += x2v.x; v1 += x2v.y; v2 += x2v.z; v3 += x2v.w;
    }

    float s = v0 + v1 + v2 + v3;
#pragma unroll
    for (int o = 16; o; o >>= 1) s += __shfl_xor_sync(0xffffffffu, s, o);
    if ((tid & 31) == 0) sred[tid >> 5] = s;
    __syncthreads();
    float mean = (sred[0] + sred[1] + sred[2] + sred[3]) * (1.f / 512.f);

    v0 -= mean; v1 -= mean; v2 -= mean; v3 -= mean;
    float sq = v0 * v0 + v1 * v1 + v2 * v2 + v3 * v3;
#pragma unroll
    for (int o = 16; o; o >>= 1) sq += __shfl_xor_sync(0xffffffffu, sq, o);
    if ((tid & 31) == 0) sred[4 + (tid >> 5)] = sq;
    __syncthreads();
    float var = (sred[4] + sred[5] + sred[6] + sred[7]) * (1.f / 512.f);
    float rstd = rsqrtf(var + 1e-5f);

    float4 g = ((const float4*)gamma)[tid];
    float4 be = ((const float4*)beta)[tid];
    float o0 = v0 * rstd * g.x + be.x;
    float o1 = v1 * rstd * g.y + be.y;
    float o2 = v2 * rstd * g.z + be.z;
    float o3 = v3 * rstd * g.w + be.w;
    float4 o; o.x = o0; o.y = o1; o.z = o2; o.w = o3;
    ((float4*)(h + (size_t)b * 512))[tid] = o;

    __half2* d = (__half2*)(hH + (size_t)b * 512 + tid * 4);
    d[0] = __floats2half2_rn(o0, o1);
    d[1] = __floats2half2_rn(o2, o3);
}

// ---------------- init ----------------
__global__ void __launch_bounds__(128) init_k(
    const int* __restrict__ e1, const int* __restrict__ qi,
    const float* __restrict__ emb_e, const float* __restrict__ emb_r,
    float* __restrict__ h, __half* __restrict__ actH,
    float* __restrict__ outq, int writeq)
{
    const int b = blockIdx.x, t = threadIdx.x;
    const float* se = emb_e + (size_t)e1[b] * 512;
    const float* sr = emb_r + (size_t)qi[b] * 512;
    for (int j = t; j < 512; j += 128) {
        float hv = se[j];
        h[(size_t)b * 512 + j] = hv;
        actH[(size_t)b * 512 + j] = __float2half_rn(hv);
        float q = sr[j];
        actH[(size_t)(BB + b) * 512 + j] = __float2half_rn(q);
        if (writeq) outq[(size_t)b * 512 + j] = q;
    }
}

__global__ void copy_k(float* __restrict__ out, const float* __restrict__ in)
{
    int i = blockIdx.x * 256 + threadIdx.x;
    out[i] = in[i];
}

// ---------------- launch ----------------
extern "C" void kernel_launch(void* const* d_in, const int* in_sizes, int n_in,
                              void* d_out, int out_size)
{
    const int*   e1    = (const int*)d_in[0];
    const int*   qidx  = (const int*)d_in[1];
    const int*   nbr_r = (const int*)d_in[2];
    const int*   nbr_e = (const int*)d_in[3];
    const float* masks = (const float*)d_in[4];
    const float* emb_e = (const float*)d_in[5];
    const float* emb_r = (const float*)d_in[6];
    const float* msg_W = (const float*)d_in[7];
    const float* msg_b = (const float*)d_in[8];
    const float* Wq    = (const float*)d_in[9];
    const float* bq    = (const float*)d_in[10];
    const float* Wk    = (const float*)d_in[11];
    const float* bk    = (const float*)d_in[12];
    const float* Wv    = (const float*)d_in[13];
    const float* bv    = (const float*)d_in[14];
    const float* ffW1  = (const float*)d_in[15];
    const float* ffb1  = (const float*)d_in[16];
    const float* ffW2  = (const float*)d_in[17];
    const float* ffb2  = (const float*)d_in[18];
    const float* ln1g  = (const float*)d_in[19];
    const float* ln1b  = (const float*)d_in[20];
    const float* ln2g  = (const float*)d_in[21];
    const float* ln2b  = (const float*)d_in[22];
    float* out = (float*)d_out;

    __half *p_embeH, *p_eW2H, *p_embrH, *p_actH, *p_ctxH, *p_ffH, *p_rW1H;
    __half *p_W2h, *p_W1h, *p_Wcomb, *p_Wkh, *p_Wvh, *p_F1h, *p_F2h;
    float *p_bias2, *p_Khat, *p_h, *p_hw0qh, *p_x;
    cudaGetSymbolAddress((void**)&p_embeH, g_embeH);
    cudaGetSymbolAddress((void**)&p_eW2H,  g_eW2H);
    cudaGetSymbolAddress((void**)&p_embrH, g_embrH);
    cudaGetSymbolAddress((void**)&p_actH,  g_actH);
    cudaGetSymbolAddress((void**)&p_ctxH,  g_ctxH);
    cudaGetSymbolAddress((void**)&p_ffH,   g_ffH);
    cudaGetSymbolAddress((void**)&p_rW1H,  g_rW1H);
    cudaGetSymbolAddress((void**)&p_W2h,   g_W2h);
    cudaGetSymbolAddress((void**)&p_W1h,   g_W1h);
    cudaGetSymbolAddress((void**)&p_Wcomb, g_Wcomb);
    cudaGetSymbolAddress((void**)&p_Wkh,   g_Wkh);
    cudaGetSymbolAddress((void**)&p_Wvh,   g_Wvh);
    cudaGetSymbolAddress((void**)&p_F1h,   g_F1h);
    cudaGetSymbolAddress((void**)&p_F2h,   g_F2h);
    cudaGetSymbolAddress((void**)&p_bias2, g_bias2);
    cudaGetSymbolAddress((void**)&p_Khat,  g_Khat);
    cudaGetSymbolAddress((void**)&p_h,     g_h);
    cudaGetSymbolAddress((void**)&p_hw0qh, g_hw0qh);
    cudaGetSymbolAddress((void**)&p_x,     g_x);

    const int SMK_128 = 512 + 3 * ((128 + 128) * 128);  // 98816
    const int SMK_64  = 512 + 3 * ((128 + 64) * 128);   // 74240
    cudaFuncSetAttribute((gemm_f2<128, 0>), cudaFuncAttributeMaxDynamicSharedMemorySize, SMK_128);
    cudaFuncSetAttribute((gemm_f2<128, 1>), cudaFuncAttributeMaxDynamicSharedMemorySize, SMK_128);
    cudaFuncSetAttribute((gemm_f2<64, 0>),  cudaFuncAttributeMaxDynamicSharedMemorySize, SMK_64);

    int writeq = (out_size >= 2 * BB * DD) ? 1 : 0;
    init_k<<<BB, 128>>>(e1, qidx, emb_e, emb_r, p_h, p_actH, out + (size_t)BB * DD, writeq);
    convT_k<<<dim3(8, 8, 1), 256>>>(msg_W + 1024 * 512, 512, 64, 0, 512, p_W2h, 0);
    convA_h<<<EE, 128>>>(emb_e, p_embeH);
    // eW2 = emb_e @ W2 + msg_b
    gemm_f2<128, 1><<<dim3(4, (EE + 127) / 128), 256, SMK_128>>>(
        p_embeH, 512, 0, nullptr, EE, p_W2h, 0, 512,
        msg_b, 0, p_eW2H, 512, 0, 0, 0, 0, 0);

    convT_k<<<dim3(8, 8, 1), 256>>>(msg_W + 512 * 512, 512, 64, 0, 512, p_W1h, 0);
    convA_h<<<RR, 128>>>(emb_r, p_embrH);
    biasfill_k<<<LL, 256>>>(bq, p_bias2);
    convT_k<<<dim3(8, 8, LL), 256>>>(msg_W, 512, 64, 0, 512, p_Wcomb, 524288);
    convT_k<<<dim3(8, 8, LL), 256>>>(Wq, 64, 32768, 262144, 512, p_Wcomb + 262144, 524288);
    convT_k<<<dim3(8, 8, LL), 256>>>(Wk, 64, 32768, 262144, 512, p_Wkh, 262144);
    convT_k<<<dim3(8, 8, LL), 256>>>(Wv, 64, 32768, 262144, 512, p_Wvh, 262144);
    convT_k<<<dim3(8, 32, LL), 256>>>(ffW1, 2048, 64, 1048576, 512, p_F1h, 1048576);
    convT_k<<<dim3(32, 8, LL), 256>>>(ffW2, 512, 64, 1048576, 2048, p_F2h, 1048576);

    // rW1H = half(emb_r @ W1)
    gemm_f2<128, 1><<<dim3(4, 4), 256, SMK_128>>>(
        p_embrH, 512, 0, nullptr, RR, p_W1h, 0, 512,
        nullptr, 0, p_rW1H, 512, 0, 0, 0, 0, 0);
    // Khat[l] = emb_r @ Wk[l] + bk[l]
    gemm_f2<128, 0><<<dim3(4, 4, LL), 256, SMK_128>>>(
        p_embrH, 512, 0, nullptr, RR, p_Wkh, 262144, 512,
        bk, 512, p_Khat, 512, 0, (long long)RR * 512, 0, 0, 0);

    for (int l = 0; l < LL; l++) {
        // z=0: hW0 = h @ W0; z=1: qh = embq @ Wq[l] + bq[l]
        gemm_f2<128, 0><<<dim3(4, 16, 2), 256, SMK_128>>>(
            p_actH, 512, (long long)BB * 512, nullptr, BB,
            p_Wcomb + (size_t)l * 2 * 262144, 262144, 512,
            p_bias2 + l * 1024, 512,
            p_hw0qh, 512, 0, (long long)BB * 512, 0, 0, 0);
        attn_k<<<BB, 256>>>(p_hw0qh + (size_t)BB * 512, p_Khat + (size_t)l * RR * 512,
                            nbr_r, nbr_e, masks, p_hw0qh, p_eW2H, p_rW1H, p_ctxH);
        // x = ctx @ Wv[l] + bv[l] (z = head)
        gemm_f2<64, 0><<<dim3(1, 16, 8), 256, SMK_64>>>(
            p_ctxH, 4096, 512, nullptr, BB,
            p_Wvh + (size_t)l * 262144, 32768, 512,
            bv + l * 512, 0, p_x, 512, 64, 0, 0, 0, 0);
        ln_k<<<BB, 128>>>(p_h, p_x, nullptr, ln1g + l * 512, ln1b + l * 512, p_actH);
        // ffH = fp16(relu(h @ F1 + b1))
        gemm_f2<128, 1><<<dim3(16, 16), 256, SMK_128>>>(
            p_actH, 512, 0, nullptr, BB,
            p_F1h + (size_t)l * 1048576, 0, 512,
            ffb1 + l * 2048, 0, p_ffH, 2048, 0, 0, 0, 0, 1);
        // x0/x1 = split-K halves of ff @ F2 (+ b2 on z=0); 32 chunks -> 16 per z
        gemm_f2<128, 0><<<dim3(4, 16, 2), 256, SMK_128>>>(
            p_ffH, 2048, 0, nullptr, BB,
            p_F2h + (size_t)l * 1048576, 0, 2048,
            ffb2 + l * 512, 0, p_x, 512, 0, (long long)BB * 512, 1, 16, 0);
        ln_k<<<BB, 128>>>(p_h, p_x, p_x + (size_t)BB * 512, ln2g + l * 512, ln2b + l * 512, p_actH);
    }

    copy_k<<<(BB * DD) / 256, 256>>>(out, p_h);
}